// round 13
// baseline (speedup 1.0000x reference)
#include <cuda_runtime.h>
#include <math.h>

#define TT   200
#define BB   1024
#define DD   128
#define TOBS 140
#define LL   20
#define LATD 32
#define GU   200
#define UNI  100
#define GIN  168
#define ROWS 8
#define NTHR 512
#define NBLK (BB / ROWS)

#define KH   84

#define SM_FLOATS 45224

__device__ float g_colsum[3 * GU];

__device__ __forceinline__ float fast_tanh(float x) {
    float xc = fminf(fmaxf(x, -9.f), 9.f);
    float e = __expf(2.f * xc);
    return __fdividef(e - 1.f, e + 1.f);
}
__device__ __forceinline__ float fast_sigmoid(float x) {
    return __fdividef(1.f, 1.f + __expf(-x));
}

__global__ void colsum_kernel(const float* __restrict__ uw1,
                              const float* __restrict__ rw1,
                              const float* __restrict__ nw1) {
    int j = threadIdx.x;
    const float* w = (blockIdx.x == 0) ? uw1 : (blockIdx.x == 1 ? rw1 : nw1);
    float sacc = 0.f;
    for (int k = GIN; k < 2 * LL + 2 * DD; ++k) sacc += w[k * GU + j];
    g_colsum[blockIdx.x * GU + j] = sacc;
}

#define BFLY(NR, a)                                                     \
    _Pragma("unroll")                                                   \
    for (int m_ = 1; m_ < (NR); m_ <<= 1) {                             \
        _Pragma("unroll")                                               \
        for (int r_ = 0; r_ < 8; ++r_)                                  \
            a[r_] += __shfl_xor_sync(0xffffffffu, a[r_], m_);           \
    }

// ---- GRU layer1 dual (u,r): K-split 2, even/odd ping-pong prefetch ----
__device__ __forceinline__ void gru_l1_dual_ks(const float* __restrict__ wA,
                                               const float* __restrict__ wB,
                                               const float* __restrict__ ycT,
                                               float* __restrict__ pU,
                                               float* __restrict__ pR,
                                               int j, int ks) {
    float aA[8], aB[8];
#pragma unroll
    for (int r = 0; r < 8; ++r) { aA[r] = 0.f; aB[r] = 0.f; }
    const float* pA = wA + (size_t)ks * KH * GU + j;
    const float* pB = wB + (size_t)ks * KH * GU + j;
    const float* yc = ycT + ks * KH * 8;
    float wa0[6], wb0[6], wa1[6], wb1[6];
#pragma unroll
    for (int kk = 0; kk < 6; ++kk) { wa0[kk] = pA[kk * GU]; wb0[kk] = pB[kk * GU]; }
#pragma unroll 1
    for (int t = 0; t < 14; t += 2) {
#pragma unroll
        for (int kk = 0; kk < 6; ++kk) {
            wa1[kk] = pA[((t + 1) * 6 + kk) * GU];
            wb1[kk] = pB[((t + 1) * 6 + kk) * GU];
        }
#pragma unroll
        for (int kk = 0; kk < 6; ++kk) {
            int k = t * 6 + kk;
            float4 y0 = *(const float4*)(yc + k * 8);
            float4 y1 = *(const float4*)(yc + k * 8 + 4);
            float w0 = wa0[kk], w1 = wb0[kk];
            aA[0] += y0.x * w0; aA[1] += y0.y * w0; aA[2] += y0.z * w0; aA[3] += y0.w * w0;
            aA[4] += y1.x * w0; aA[5] += y1.y * w0; aA[6] += y1.z * w0; aA[7] += y1.w * w0;
            aB[0] += y0.x * w1; aB[1] += y0.y * w1; aB[2] += y0.z * w1; aB[3] += y0.w * w1;
            aB[4] += y1.x * w1; aB[5] += y1.y * w1; aB[6] += y1.z * w1; aB[7] += y1.w * w1;
        }
        if (t + 2 < 14) {
#pragma unroll
            for (int kk = 0; kk < 6; ++kk) {
                wa0[kk] = pA[((t + 2) * 6 + kk) * GU];
                wb0[kk] = pB[((t + 2) * 6 + kk) * GU];
            }
        }
#pragma unroll
        for (int kk = 0; kk < 6; ++kk) {
            int k = (t + 1) * 6 + kk;
            float4 y0 = *(const float4*)(yc + k * 8);
            float4 y1 = *(const float4*)(yc + k * 8 + 4);
            float w0 = wa1[kk], w1 = wb1[kk];
            aA[0] += y0.x * w0; aA[1] += y0.y * w0; aA[2] += y0.z * w0; aA[3] += y0.w * w0;
            aA[4] += y1.x * w0; aA[5] += y1.y * w0; aA[6] += y1.z * w0; aA[7] += y1.w * w0;
            aB[0] += y0.x * w1; aB[1] += y0.y * w1; aB[2] += y0.z * w1; aB[3] += y0.w * w1;
            aB[4] += y1.x * w1; aB[5] += y1.y * w1; aB[6] += y1.z * w1; aB[7] += y1.w * w1;
        }
    }
    float* u = pU + ks * 1600 + j * 8;
    float* rr = pR + ks * 1600 + j * 8;
    *(float4*)u        = make_float4(aA[0], aA[1], aA[2], aA[3]);
    *(float4*)(u + 4)  = make_float4(aA[4], aA[5], aA[6], aA[7]);
    *(float4*)rr       = make_float4(aB[0], aB[1], aB[2], aB[3]);
    *(float4*)(rr + 4) = make_float4(aB[4], aB[5], aB[6], aB[7]);
}

__device__ __forceinline__ void gru_l1_single_ks(const float* __restrict__ wA,
                                                 const float* __restrict__ ycT,
                                                 float* __restrict__ pN,
                                                 int j, int ks) {
    float aA[8];
#pragma unroll
    for (int r = 0; r < 8; ++r) aA[r] = 0.f;
    const float* pA = wA + (size_t)ks * KH * GU + j;
    const float* yc = ycT + ks * KH * 8;
    float wa0[12], wa1[12];
#pragma unroll
    for (int kk = 0; kk < 12; ++kk) wa0[kk] = pA[kk * GU];
#pragma unroll 1
    for (int t = 0; t < 7; t += 2) {
        if (t + 1 < 7) {
#pragma unroll
            for (int kk = 0; kk < 12; ++kk) wa1[kk] = pA[((t + 1) * 12 + kk) * GU];
        }
#pragma unroll
        for (int kk = 0; kk < 12; ++kk) {
            int k = t * 12 + kk;
            float4 y0 = *(const float4*)(yc + k * 8);
            float4 y1 = *(const float4*)(yc + k * 8 + 4);
            float w0 = wa0[kk];
            aA[0] += y0.x * w0; aA[1] += y0.y * w0; aA[2] += y0.z * w0; aA[3] += y0.w * w0;
            aA[4] += y1.x * w0; aA[5] += y1.y * w0; aA[6] += y1.z * w0; aA[7] += y1.w * w0;
        }
        if (t + 2 < 7) {
#pragma unroll
            for (int kk = 0; kk < 12; ++kk) wa0[kk] = pA[((t + 2) * 12 + kk) * GU];
        }
        if (t + 1 < 7) {
#pragma unroll
            for (int kk = 0; kk < 12; ++kk) {
                int k = (t + 1) * 12 + kk;
                float4 y0 = *(const float4*)(yc + k * 8);
                float4 y1 = *(const float4*)(yc + k * 8 + 4);
                float w0 = wa1[kk];
                aA[0] += y0.x * w0; aA[1] += y0.y * w0; aA[2] += y0.z * w0; aA[3] += y0.w * w0;
                aA[4] += y1.x * w0; aA[5] += y1.y * w0; aA[6] += y1.z * w0; aA[7] += y1.w * w0;
            }
        }
    }
    float* p = pN + ks * 1600 + j * 8;
    *(float4*)p       = make_float4(aA[0], aA[1], aA[2], aA[3]);
    *(float4*)(p + 4) = make_float4(aA[4], aA[5], aA[6], aA[7]);
}

// encoder MLP layer1 only (400 thr, 2 rows each, direct)
__device__ __forceinline__ void enc_l1(const float* __restrict__ ew1,
                                       const float* __restrict__ eb1,
                                       const float* __restrict__ ymT,
                                       float* __restrict__ hencT, int tid) {
    if (tid < 400) {
        int j = tid % UNI, rq = tid / UNI;
        float a0 = eb1[j], a1 = a0;
#pragma unroll
        for (int k = 0; k < LL; ++k) {
            float w = ew1[k * UNI + j];
            float2 yv = *(const float2*)(ymT + k * 8 + 2 * rq);
            a0 += yv.x * w; a1 += yv.y * w;
        }
        *(float2*)(hencT + j * 8 + 2 * rq) = make_float2(fast_tanh(a0), fast_tanh(a1));
    }
}

// encoder MLP l2 + RK4-stage update fused (butterfly over ks8); stage 0 also prefetches truth
__device__ __forceinline__ void enc_l2_fused(const float* __restrict__ ew2p,
                                             const float* __restrict__ eb2,
                                             const float* __restrict__ hencT,
                                             float* __restrict__ accT,
                                             float* __restrict__ ycT,
                                             float* __restrict__ y,
                                             const float* __restrict__ truth,
                                             int io, int b0, int stage, float dt, int tid) {
    if (tid < 160) {
        int jj = tid >> 3, ks = tid & 7;
        int k0 = (ks < 4) ? ks * 13 : 52 + (ks - 4) * 12;
        int kn = (ks < 4) ? 13 : 12;
        float a[8];
#pragma unroll
        for (int r = 0; r < 8; ++r) a[r] = 0.f;
#pragma unroll 4
        for (int k = k0; k < k0 + kn; ++k) {
            float w = ew2p[k * 21 + jj];
            float4 y0 = *(const float4*)(hencT + k * 8);
            float4 y1 = *(const float4*)(hencT + k * 8 + 4);
            a[0] += y0.x * w; a[1] += y0.y * w; a[2] += y0.z * w; a[3] += y0.w * w;
            a[4] += y1.x * w; a[5] += y1.y * w; a[6] += y1.z * w; a[7] += y1.w * w;
        }
        BFLY(8, a);
        if (ks == 0) {
            float kv[8], yv[8];
#pragma unroll
            for (int r = 0; r < 8; ++r) { kv[r] = a[r] + eb2[jj]; yv[r] = y[r * 40 + jj]; }
            if (stage == 0) {
#pragma unroll
                for (int r = 0; r < 8; ++r) { accT[jj * 8 + r] = kv[r]; ycT[jj * 8 + r] = yv[r] + 0.5f * dt * kv[r]; }
            } else if (stage == 1) {
#pragma unroll
                for (int r = 0; r < 8; ++r) { accT[jj * 8 + r] += 2.f * kv[r]; ycT[jj * 8 + r] = yv[r] + 0.5f * dt * kv[r]; }
            } else if (stage == 2) {
#pragma unroll
                for (int r = 0; r < 8; ++r) { accT[jj * 8 + r] += 2.f * kv[r]; ycT[jj * 8 + r] = yv[r] + dt * kv[r]; }
            } else {
#pragma unroll
                for (int r = 0; r < 8; ++r) {
                    float ynew = yv[r] + dt * (1.f / 6.f) * (accT[jj * 8 + r] + kv[r]);
                    y[r * 40 + jj] = ynew;
                    ycT[jj * 8 + r] = ynew;
                }
            }
        }
    } else if (stage == 0) {
        const float* trow = truth + (size_t)io * (BB * DD) + (size_t)b0 * DD;
        for (int i = tid - 160; i < 1024; i += 352) {
            int k = i >> 3, r = i & 7;
            ycT[(40 + k) * 8 + r] = trow[(size_t)r * DD + k];
        }
    }
}

// decoder l1 (400 thr direct)
__device__ __forceinline__ void dec_l1(const float* __restrict__ dw1,
                                       const float* __restrict__ db1,
                                       const float* __restrict__ zin,
                                       float* __restrict__ h1T, int tid) {
    if (tid < 400) {
        int j = tid % UNI, rq = tid / UNI;
        float a0 = db1[j], a1 = a0;
#pragma unroll 8
        for (int k = 0; k < LATD; ++k) {
            float w = dw1[k * UNI + j];
            float2 zv = *(const float2*)(zin + k * 8 + 2 * rq);
            a0 += zv.x * w; a1 += zv.y * w;
        }
        *(float2*)(h1T + j * 8 + 2 * rq) = make_float2(fast_tanh(a0), fast_tanh(a1));
    }
}

// decoder l2 fused (butterfly over ks4); 416 thr (13 full warps), j>=100 lanes compute garbage
__device__ __forceinline__ void dec_l2f(const float* __restrict__ dw2p,
                                        const float* __restrict__ db2,
                                        const float* __restrict__ h1T,
                                        float* __restrict__ h2T, int tid) {
    if (tid < 416) {
        int j = tid >> 2, ks = tid & 3;
        float a[8];
#pragma unroll
        for (int r = 0; r < 8; ++r) a[r] = 0.f;
#pragma unroll 5
        for (int k = ks * 25; k < ks * 25 + 25; ++k) {
            float w = dw2p[k * 104 + j];
            float4 z0 = *(const float4*)(h1T + k * 8);
            float4 z1 = *(const float4*)(h1T + k * 8 + 4);
            a[0] += z0.x * w; a[1] += z0.y * w; a[2] += z0.z * w; a[3] += z0.w * w;
            a[4] += z1.x * w; a[5] += z1.y * w; a[6] += z1.z * w; a[7] += z1.w * w;
        }
        BFLY(4, a);
        if (ks == 0 && j < 100) {
            float b = db2[j];
            float4 o;
            o.x = fast_tanh(a[0] + b); o.y = fast_tanh(a[1] + b);
            o.z = fast_tanh(a[2] + b); o.w = fast_tanh(a[3] + b);
            *(float4*)(h2T + j * 8) = o;
            o.x = fast_tanh(a[4] + b); o.y = fast_tanh(a[5] + b);
            o.z = fast_tanh(a[6] + b); o.w = fast_tanh(a[7] + b);
            *(float4*)(h2T + j * 8 + 4) = o;
        }
    }
}

// decoder l3 fused (butterfly over ks8) + RK4 update; stage 0 also projects out[pti]
__device__ __forceinline__ void dec_l3f(const float* __restrict__ dw3p,
                                        const float* __restrict__ db3,
                                        const float* __restrict__ h2T,
                                        float* __restrict__ zT,
                                        float* __restrict__ ztmpT,
                                        float* __restrict__ zaccT,
                                        int tid, int stage, float dt,
                                        const float* __restrict__ ow,
                                        const float* __restrict__ ob,
                                        float* __restrict__ outp, int b0, int pti) {
    if (tid < 256) {
        int jj = tid >> 3, ks = tid & 7;
        int k0 = (ks < 4) ? ks * 13 : 52 + (ks - 4) * 12;
        int kn = (ks < 4) ? 13 : 12;
        float a[8];
#pragma unroll
        for (int r = 0; r < 8; ++r) a[r] = 0.f;
#pragma unroll 4
        for (int k = k0; k < k0 + kn; ++k) {
            float w = dw3p[k * 33 + jj];
            float4 z0 = *(const float4*)(h2T + k * 8);
            float4 z1 = *(const float4*)(h2T + k * 8 + 4);
            a[0] += z0.x * w; a[1] += z0.y * w; a[2] += z0.z * w; a[3] += z0.w * w;
            a[4] += z1.x * w; a[5] += z1.y * w; a[6] += z1.z * w; a[7] += z1.w * w;
        }
        BFLY(8, a);
        if (ks == 0) {
            float b = db3[jj];
            float kv[8], zv[8];
#pragma unroll
            for (int r = 0; r < 8; ++r) { kv[r] = a[r] + b; zv[r] = zT[jj * 8 + r]; }
            if (stage == 0) {
#pragma unroll
                for (int r = 0; r < 8; ++r) { zaccT[jj * 8 + r] = kv[r]; ztmpT[jj * 8 + r] = zv[r] + 0.5f * dt * kv[r]; }
            } else if (stage == 1) {
#pragma unroll
                for (int r = 0; r < 8; ++r) { zaccT[jj * 8 + r] += 2.f * kv[r]; ztmpT[jj * 8 + r] = zv[r] + 0.5f * dt * kv[r]; }
            } else if (stage == 2) {
#pragma unroll
                for (int r = 0; r < 8; ++r) { zaccT[jj * 8 + r] += 2.f * kv[r]; ztmpT[jj * 8 + r] = zv[r] + dt * kv[r]; }
            } else {
#pragma unroll
                for (int r = 0; r < 8; ++r) zT[jj * 8 + r] = zv[r] + dt * (1.f / 6.f) * (zaccT[jj * 8 + r] + kv[r]);
            }
        }
    } else if (stage == 0 && tid < 384) {
        int d = tid - 256;
        float a[8];
        float b = ob[d];
#pragma unroll
        for (int r = 0; r < 8; ++r) a[r] = b;
#pragma unroll 8
        for (int k = 0; k < LATD; ++k) {
            float w = ow[k * DD + d];
            float4 z0 = *(const float4*)(zT + k * 8);
            float4 z1 = *(const float4*)(zT + k * 8 + 4);
            a[0] += z0.x * w; a[1] += z0.y * w; a[2] += z0.z * w; a[3] += z0.w * w;
            a[4] += z1.x * w; a[5] += z1.y * w; a[6] += z1.z * w; a[7] += z1.w * w;
        }
#pragma unroll
        for (int r = 0; r < 8; ++r)
            outp[(size_t)(b0 + r) * (TT * DD) + (size_t)pti * DD + d] = a[r];
    }
}

extern "C" __global__ void __launch_bounds__(NTHR, 1)
latent_ode_main(const float* __restrict__ truth, const float* __restrict__ tarr,
                const int* __restrict__ obs_idx, const float* __restrict__ eps,
                const float* __restrict__ ew1g, const float* __restrict__ eb1g,
                const float* __restrict__ ew2g, const float* __restrict__ eb2g,
                const float* __restrict__ uw1, const float* __restrict__ ub1g,
                const float* __restrict__ uw2g, const float* __restrict__ ub2g,
                const float* __restrict__ rw1, const float* __restrict__ rb1g,
                const float* __restrict__ rw2g, const float* __restrict__ rb2g,
                const float* __restrict__ nw1, const float* __restrict__ nb1g,
                const float* __restrict__ nw2g, const float* __restrict__ nb2g,
                const float* __restrict__ z0w1, const float* __restrict__ z0b1,
                const float* __restrict__ z0w2, const float* __restrict__ z0b2,
                const float* __restrict__ dw1g, const float* __restrict__ db1g,
                const float* __restrict__ dw2g, const float* __restrict__ db2g,
                const float* __restrict__ dw3g, const float* __restrict__ db3g,
                const float* __restrict__ owg, const float* __restrict__ obg,
                float* __restrict__ out) {
    extern __shared__ float s[];
    const int tid = threadIdx.x;
    const int b0 = blockIdx.x * ROWS;

    float* zT = s;           // [32][8] k-major, persistent
    float* P  = s + 256;

    // ---------------- encoder smem layout ----------------
    float* ew1   = P;            // 2000
    float* ew2p  = P + 2000;     // 2100 (stride 21)
    float* eb1   = P + 4100;     // 100
    float* eb2   = P + 4200;     // 24
    float* uw2p  = P + 4224;     // 8800 (stride 44)
    float* rw2p  = P + 13024;    // 8800
    float* nw2p  = P + 21824;    // 8800
    float* ub1   = P + 30624;    // 200
    float* rb1   = P + 30824;    // 200
    float* nb1   = P + 31024;    // 200
    float* ub2   = P + 31224;    // 40
    float* rb2   = P + 31264;    // 40
    float* nb2   = P + 31304;    // 40
    float* csu   = P + 31344;    // 200
    float* csr   = P + 31544;    // 200
    float* csn   = P + 31744;    // 200
    float* y     = P + 31944;    // 320  [8][40]
    float* ycT   = P + 32264;    // 1344 [168][8]; [0:160) = ym RK4 scratch
    float* accT  = P + 33608;    // 160
    float* hencT = P + 33768;    // 800
    float* hTa   = P + 34568;    // 1600
    float* hTb   = P + 36168;    // 1600
    float* pL1   = P + 37768;    // 6400
    float* u_    = P + 44168;    // 320
    float* dts   = P + 44488;    // 140
    float* iob   = P + 44628;    // 140
    float* ddt   = P + 44768;    // 200  (beyond decoder alias region)

    for (int i = tid; i < 2000; i += NTHR) {
        ew1[i] = ew1g[i];
        ew2p[(i / 20) * 21 + (i % 20)] = ew2g[i];
    }
    for (int i = tid; i < 100;  i += NTHR) eb1[i] = eb1g[i];
    for (int i = tid; i < 20;   i += NTHR) eb2[i] = eb2g[i];
    for (int i = tid; i < 8000; i += NTHR) {
        int off = (i / 40) * 44 + (i % 40);
        uw2p[off] = uw2g[i]; rw2p[off] = rw2g[i]; nw2p[off] = nw2g[i];
    }
    for (int i = tid; i < 200;  i += NTHR) {
        ub1[i] = ub1g[i]; rb1[i] = rb1g[i]; nb1[i] = nb1g[i];
        csu[i] = g_colsum[i]; csr[i] = g_colsum[200 + i]; csn[i] = g_colsum[400 + i];
    }
    for (int i = tid; i < 40; i += NTHR) { ub2[i] = ub2g[i]; rb2[i] = rb2g[i]; nb2[i] = nb2g[i]; }
    for (int i = tid; i < ROWS * 40; i += NTHR) y[i] = 0.f;
    for (int i = tid; i < 320; i += NTHR) ycT[i] = 0.f;
    for (int i = tid; i < TOBS; i += NTHR) {
        int io = obs_idx[TOBS - 1 - i];
        iob[i] = __int_as_float(io);
        dts[i] = (i > 0) ? (tarr[io] - tarr[obs_idx[TOBS - i]]) : 0.f;
    }
    for (int i = tid; i < TT - 1; i += NTHR) ddt[i] = tarr[i + 1] - tarr[i];
    __syncthreads();

    // ================= encoder scan =================
    for (int st = 0; st < TOBS; ++st) {
        int io = __float_as_int(iob[st]);
        float dt = dts[st];

        // ---- RK4: 4 × (l1 | l2+update fused) ----
#pragma unroll 1
        for (int stg = 0; stg < 4; ++stg) {
            enc_l1(ew1, eb1, ycT, hencT, tid);
            __syncthreads();
            enc_l2_fused(ew2p, eb2, hencT, accT, ycT, y, truth, io, b0, stg, dt, tid);
            __syncthreads();
        }

        // ---- u,r layer1 (K-split 2, 400 thr) ----
        if (tid < 400)
            gru_l1_dual_ks(uw1, rw1, ycT, pL1, pL1 + 3200, tid % GU, tid / GU);
        __syncthreads();
        for (int i = tid; i < 3200; i += NTHR) {
            int g = i / 1600, rem = i % 1600, j = rem >> 3;
            float base = g ? (csr[j] + rb1[j]) : (csu[j] + ub1[j]);
            float v = pL1[g * 3200 + rem] + pL1[g * 3200 + 1600 + rem] + base;
            (g ? hTb : hTa)[rem] = fast_tanh(v);
        }
        __syncthreads();

        // ---- u,r layer2 fused (butterfly over ks4, 320 thr) ----
        if (tid < 320) {
            int q = tid >> 2, ks = tid & 3;
            int g = (q >= 40), jj = g ? (q - 40) : q;
            const float* hT = g ? hTb : hTa;
            const float* w2 = g ? rw2p : uw2p;
            float a[8];
#pragma unroll
            for (int r = 0; r < 8; ++r) a[r] = 0.f;
#pragma unroll 10
            for (int k = ks * 50; k < ks * 50 + 50; ++k) {
                float w = w2[k * 44 + jj];
                float4 h0 = *(const float4*)(hT + k * 8);
                float4 h1 = *(const float4*)(hT + k * 8 + 4);
                a[0] += h0.x * w; a[1] += h0.y * w; a[2] += h0.z * w; a[3] += h0.w * w;
                a[4] += h1.x * w; a[5] += h1.y * w; a[6] += h1.z * w; a[7] += h1.w * w;
            }
            BFLY(4, a);
            if (ks == 0) {
                float b = g ? rb2[jj] : ub2[jj];
                if (g) {
#pragma unroll
                    for (int r = 0; r < 8; ++r)
                        ycT[jj * 8 + r] *= fast_sigmoid(a[r] + b);
                } else {
#pragma unroll
                    for (int r = 0; r < 8; ++r)
                        u_[r * 40 + jj] = fast_sigmoid(a[r] + b);
                }
            }
        }
        __syncthreads();

        // ---- n layer1 (K-split 2, 400 thr; ycT already r-scaled) ----
        if (tid < 400)
            gru_l1_single_ks(nw1, ycT, pL1, tid % GU, tid / GU);
        __syncthreads();
        for (int i = tid; i < 1600; i += NTHR) {
            int j = i >> 3;
            hTa[i] = fast_tanh(pL1[i] + pL1[1600 + i] + csn[j] + nb1[j]);
        }
        __syncthreads();

        // ---- n layer2 fused (butterfly over ks8, 320 thr) ----
        if (tid < 320) {
            int jj = tid >> 3, ks = tid & 7;   // K = 200/8 = 25
            float a[8];
#pragma unroll
            for (int r = 0; r < 8; ++r) a[r] = 0.f;
#pragma unroll 5
            for (int k = ks * 25; k < ks * 25 + 25; ++k) {
                float w = nw2p[k * 44 + jj];
                float4 h0 = *(const float4*)(hTa + k * 8);
                float4 h1 = *(const float4*)(hTa + k * 8 + 4);
                a[0] += h0.x * w; a[1] += h0.y * w; a[2] += h0.z * w; a[3] += h0.w * w;
                a[4] += h1.x * w; a[5] += h1.y * w; a[6] += h1.z * w; a[7] += h1.w * w;
            }
            BFLY(8, a);
            if (ks == 0) {
                float b = nb2[jj];
#pragma unroll
                for (int r = 0; r < 8; ++r) {
                    float v = a[r] + b;
                    float val = (jj < LL) ? v : fabsf(v);
                    float uu = u_[r * 40 + jj];
                    float ynew = (1.f - uu) * val + uu * y[r * 40 + jj];
                    y[r * 40 + jj] = ynew;
                    ycT[jj * 8 + r] = ynew;
                }
            }
        }
        __syncthreads();
    }

    // ================= z0 head (once) =================
    for (int i = tid; i < ROWS * UNI; i += NTHR) {
        int r = i / UNI, j = i % UNI;
        float a = z0b1[j];
#pragma unroll 4
        for (int k = 0; k < 40; ++k) a += y[r * 40 + k] * z0w1[k * UNI + j];
        hencT[i] = fast_tanh(a);
    }
    __syncthreads();
    for (int i = tid; i < ROWS * 64; i += NTHR) {
        int r = i / 64, j = i % 64;
        float a = z0b2[j];
#pragma unroll 4
        for (int k = 0; k < UNI; ++k) a += hencT[r * UNI + k] * z0w2[k * 64 + j];
        hTa[r * 64 + j] = a;
    }
    __syncthreads();
    if (tid < 256) {
        int r = tid >> 5, j = tid & 31;
        float m = hTa[r * 64 + j];
        float sd = fabsf(hTa[r * 64 + 32 + j]);
        zT[j * 8 + r] = m + eps[(size_t)(b0 + r) * LATD + j] * sd;
    }
    __syncthreads();

    // ---------------- decoder smem layout (aliases P; ddt beyond -> safe) ----------------
    float* dw1   = P;             // 3200
    float* dw2p  = P + 3200;      // 10400 (stride 104)
    float* dw3p  = P + 13600;     // 3300 (stride 33)
    float* db1   = P + 16900;     // 104
    float* db2   = P + 17004;     // 104
    float* db3   = P + 17108;     // 32
    float* ow    = P + 17140;     // 4096
    float* ob    = P + 21236;     // 128
    float* h1T   = P + 21364;     // 800
    float* h2T   = P + 22164;     // 800
    float* ztmpT = P + 22964;     // 256
    float* zaccT = P + 23220;     // 256 (end 23476)

    for (int i = tid; i < 3200;  i += NTHR) dw1[i] = dw1g[i];
    for (int i = tid; i < 10000; i += NTHR) dw2p[(i / 100) * 104 + (i % 100)] = dw2g[i];
    for (int i = tid; i < 3200;  i += NTHR) dw3p[(i / 32) * 33 + (i % 32)] = dw3g[i];
    for (int i = tid; i < 100;   i += NTHR) { db1[i] = db1g[i]; db2[i] = db2g[i]; }
    for (int i = tid; i < 32;    i += NTHR) db3[i] = db3g[i];
    for (int i = tid; i < 4096;  i += NTHR) ow[i] = owg[i];
    for (int i = tid; i < 128;   i += NTHR) ob[i] = obg[i];
    __syncthreads();

    // ================= decoder scan: 4 stages × 3 phases each =================
    for (int ti = 1; ti < TT; ++ti) {
        float dt = ddt[ti - 1];
        // stage 1 (reads zT; l3 also projects out[ti-1] via threads 256..383)
        dec_l1(dw1, db1, zT, h1T, tid);
        __syncthreads();
        dec_l2f(dw2p, db2, h1T, h2T, tid);
        __syncthreads();
        dec_l3f(dw3p, db3, h2T, zT, ztmpT, zaccT, tid, 0, dt, ow, ob, out, b0, ti - 1);
        __syncthreads();
        // stage 2
        dec_l1(dw1, db1, ztmpT, h1T, tid);
        __syncthreads();
        dec_l2f(dw2p, db2, h1T, h2T, tid);
        __syncthreads();
        dec_l3f(dw3p, db3, h2T, zT, ztmpT, zaccT, tid, 1, dt, ow, ob, out, b0, -1);
        __syncthreads();
        // stage 3
        dec_l1(dw1, db1, ztmpT, h1T, tid);
        __syncthreads();
        dec_l2f(dw2p, db2, h1T, h2T, tid);
        __syncthreads();
        dec_l3f(dw3p, db3, h2T, zT, ztmpT, zaccT, tid, 2, dt, ow, ob, out, b0, -1);
        __syncthreads();
        // stage 4 (l3 writes zT)
        dec_l1(dw1, db1, ztmpT, h1T, tid);
        __syncthreads();
        dec_l2f(dw2p, db2, h1T, h2T, tid);
        __syncthreads();
        dec_l3f(dw3p, db3, h2T, zT, ztmpT, zaccT, tid, 3, dt, ow, ob, out, b0, -1);
        __syncthreads();
    }

    // final projection for ti = TT-1
    if (tid < DD) {
        int d = tid;
        float a[8];
        float b = ob[d];
#pragma unroll
        for (int r = 0; r < 8; ++r) a[r] = b;
#pragma unroll 8
        for (int k = 0; k < LATD; ++k) {
            float w = ow[k * DD + d];
            float4 z0 = *(const float4*)(zT + k * 8);
            float4 z1 = *(const float4*)(zT + k * 8 + 4);
            a[0] += z0.x * w; a[1] += z0.y * w; a[2] += z0.z * w; a[3] += z0.w * w;
            a[4] += z1.x * w; a[5] += z1.y * w; a[6] += z1.z * w; a[7] += z1.w * w;
        }
#pragma unroll
        for (int r = 0; r < 8; ++r)
            out[(size_t)(b0 + r) * (TT * DD) + (size_t)(TT - 1) * DD + d] = a[r];
    }
}

extern "C" void kernel_launch(void* const* d_in, const int* in_sizes, int n_in,
                              void* d_out, int out_size) {
    (void)in_sizes; (void)n_in; (void)out_size;
    size_t smem = (size_t)SM_FLOATS * sizeof(float);
    cudaFuncSetAttribute(latent_ode_main, cudaFuncAttributeMaxDynamicSharedMemorySize, (int)smem);

    colsum_kernel<<<3, GU>>>((const float*)d_in[8], (const float*)d_in[12], (const float*)d_in[16]);

    latent_ode_main<<<NBLK, NTHR, smem>>>(
        (const float*)d_in[0], (const float*)d_in[1], (const int*)d_in[2], (const float*)d_in[3],
        (const float*)d_in[4],  (const float*)d_in[5],  (const float*)d_in[6],  (const float*)d_in[7],
        (const float*)d_in[8],  (const float*)d_in[9],  (const float*)d_in[10], (const float*)d_in[11],
        (const float*)d_in[12], (const float*)d_in[13], (const float*)d_in[14], (const float*)d_in[15],
        (const float*)d_in[16], (const float*)d_in[17], (const float*)d_in[18], (const float*)d_in[19],
        (const float*)d_in[20], (const float*)d_in[21], (const float*)d_in[22], (const float*)d_in[23],
        (const float*)d_in[24], (const float*)d_in[25], (const float*)d_in[26], (const float*)d_in[27],
        (const float*)d_in[28], (const float*)d_in[29], (const float*)d_in[30], (const float*)d_in[31],
        (float*)d_out);
}

// round 14
// speedup vs baseline: 1.7900x; 1.7900x over previous
#include <cuda_runtime.h>
#include <math.h>

#define TT   200
#define BB   1024
#define DD   128
#define TOBS 140
#define LL   20
#define LATD 32
#define GU   200
#define UNI  100
#define GIN  168      /* effective K: y(40)+x(128); ones-row folded into colsum */
#define ROWS 8
#define NTHR 512
#define NBLK (BB / ROWS)

#define KH   84       /* K per half for GRU l1 split-2 */

#define SM_FLOATS 51208

__device__ float g_colsum[3 * GU];

__device__ __forceinline__ float fast_tanh(float x) {
    float xc = fminf(fmaxf(x, -9.f), 9.f);
    float e = __expf(2.f * xc);
    return __fdividef(e - 1.f, e + 1.f);
}
__device__ __forceinline__ float fast_sigmoid(float x) {
    return __fdividef(1.f, 1.f + __expf(-x));
}

__global__ void colsum_kernel(const float* __restrict__ uw1,
                              const float* __restrict__ rw1,
                              const float* __restrict__ nw1) {
    int j = threadIdx.x;
    const float* w = (blockIdx.x == 0) ? uw1 : (blockIdx.x == 1 ? rw1 : nw1);
    float sacc = 0.f;
    for (int k = GIN; k < 2 * LL + 2 * DD; ++k) sacc += w[k * GU + j];
    g_colsum[blockIdx.x * GU + j] = sacc;
}

// ---- GRU layer1 dual (u,r): K-split 2, even/odd ping-pong prefetch (tiles of 6) ----
__device__ __forceinline__ void gru_l1_dual_ks(const float* __restrict__ wA,
                                               const float* __restrict__ wB,
                                               const float* __restrict__ ycT,
                                               float* __restrict__ pU,
                                               float* __restrict__ pR,
                                               int j, int ks) {
    float aA[8], aB[8];
#pragma unroll
    for (int r = 0; r < 8; ++r) { aA[r] = 0.f; aB[r] = 0.f; }
    const float* pA = wA + (size_t)ks * KH * GU + j;
    const float* pB = wB + (size_t)ks * KH * GU + j;
    const float* yc = ycT + ks * KH * 8;
    float wa0[6], wb0[6], wa1[6], wb1[6];
#pragma unroll
    for (int kk = 0; kk < 6; ++kk) { wa0[kk] = pA[kk * GU]; wb0[kk] = pB[kk * GU]; }
#pragma unroll 1
    for (int t = 0; t < 14; t += 2) {
#pragma unroll
        for (int kk = 0; kk < 6; ++kk) {
            wa1[kk] = pA[((t + 1) * 6 + kk) * GU];
            wb1[kk] = pB[((t + 1) * 6 + kk) * GU];
        }
#pragma unroll
        for (int kk = 0; kk < 6; ++kk) {
            int k = t * 6 + kk;
            float4 y0 = *(const float4*)(yc + k * 8);
            float4 y1 = *(const float4*)(yc + k * 8 + 4);
            float w0 = wa0[kk], w1 = wb0[kk];
            aA[0] += y0.x * w0; aA[1] += y0.y * w0; aA[2] += y0.z * w0; aA[3] += y0.w * w0;
            aA[4] += y1.x * w0; aA[5] += y1.y * w0; aA[6] += y1.z * w0; aA[7] += y1.w * w0;
            aB[0] += y0.x * w1; aB[1] += y0.y * w1; aB[2] += y0.z * w1; aB[3] += y0.w * w1;
            aB[4] += y1.x * w1; aB[5] += y1.y * w1; aB[6] += y1.z * w1; aB[7] += y1.w * w1;
        }
        if (t + 2 < 14) {
#pragma unroll
            for (int kk = 0; kk < 6; ++kk) {
                wa0[kk] = pA[((t + 2) * 6 + kk) * GU];
                wb0[kk] = pB[((t + 2) * 6 + kk) * GU];
            }
        }
#pragma unroll
        for (int kk = 0; kk < 6; ++kk) {
            int k = (t + 1) * 6 + kk;
            float4 y0 = *(const float4*)(yc + k * 8);
            float4 y1 = *(const float4*)(yc + k * 8 + 4);
            float w0 = wa1[kk], w1 = wb1[kk];
            aA[0] += y0.x * w0; aA[1] += y0.y * w0; aA[2] += y0.z * w0; aA[3] += y0.w * w0;
            aA[4] += y1.x * w0; aA[5] += y1.y * w0; aA[6] += y1.z * w0; aA[7] += y1.w * w0;
            aB[0] += y0.x * w1; aB[1] += y0.y * w1; aB[2] += y0.z * w1; aB[3] += y0.w * w1;
            aB[4] += y1.x * w1; aB[5] += y1.y * w1; aB[6] += y1.z * w1; aB[7] += y1.w * w1;
        }
    }
    float* u = pU + ks * 1600 + j * 8;
    float* rr = pR + ks * 1600 + j * 8;
    *(float4*)u        = make_float4(aA[0], aA[1], aA[2], aA[3]);
    *(float4*)(u + 4)  = make_float4(aA[4], aA[5], aA[6], aA[7]);
    *(float4*)rr       = make_float4(aB[0], aB[1], aB[2], aB[3]);
    *(float4*)(rr + 4) = make_float4(aB[4], aB[5], aB[6], aB[7]);
}

// ---- GRU n layer1: K-split 2, even/odd ping-pong prefetch (tiles of 12, 7 tiles) ----
__device__ __forceinline__ void gru_l1_single_ks(const float* __restrict__ wA,
                                                 const float* __restrict__ ycT,
                                                 float* __restrict__ pN,
                                                 int j, int ks) {
    float aA[8];
#pragma unroll
    for (int r = 0; r < 8; ++r) aA[r] = 0.f;
    const float* pA = wA + (size_t)ks * KH * GU + j;
    const float* yc = ycT + ks * KH * 8;
    float wa0[12], wa1[12];
#pragma unroll
    for (int kk = 0; kk < 12; ++kk) wa0[kk] = pA[kk * GU];
#pragma unroll 1
    for (int t = 0; t < 7; t += 2) {
        if (t + 1 < 7) {
#pragma unroll
            for (int kk = 0; kk < 12; ++kk) wa1[kk] = pA[((t + 1) * 12 + kk) * GU];
        }
#pragma unroll
        for (int kk = 0; kk < 12; ++kk) {
            int k = t * 12 + kk;
            float4 y0 = *(const float4*)(yc + k * 8);
            float4 y1 = *(const float4*)(yc + k * 8 + 4);
            float w0 = wa0[kk];
            aA[0] += y0.x * w0; aA[1] += y0.y * w0; aA[2] += y0.z * w0; aA[3] += y0.w * w0;
            aA[4] += y1.x * w0; aA[5] += y1.y * w0; aA[6] += y1.z * w0; aA[7] += y1.w * w0;
        }
        if (t + 2 < 7) {
#pragma unroll
            for (int kk = 0; kk < 12; ++kk) wa0[kk] = pA[((t + 2) * 12 + kk) * GU];
        }
        if (t + 1 < 7) {
#pragma unroll
            for (int kk = 0; kk < 12; ++kk) {
                int k = (t + 1) * 12 + kk;
                float4 y0 = *(const float4*)(yc + k * 8);
                float4 y1 = *(const float4*)(yc + k * 8 + 4);
                float w0 = wa1[kk];
                aA[0] += y0.x * w0; aA[1] += y0.y * w0; aA[2] += y0.z * w0; aA[3] += y0.w * w0;
                aA[4] += y1.x * w0; aA[5] += y1.y * w0; aA[6] += y1.z * w0; aA[7] += y1.w * w0;
            }
        }
    }
    float* p = pN + ks * 1600 + j * 8;
    *(float4*)p       = make_float4(aA[0], aA[1], aA[2], aA[3]);
    *(float4*)(p + 4) = make_float4(aA[4], aA[5], aA[6], aA[7]);
}

// encoder MLP: l1 direct (400 thr, 2 rows, no reduce), l2 partials (200 thr)
// ytmpT == ycT[0:160] (aliased, k-major ym)
__device__ __forceinline__ void enc_eval(const float* __restrict__ ew1,
                                         const float* __restrict__ eb1,
                                         const float* __restrict__ ew2,
                                         const float* __restrict__ ytmpT,
                                         float* __restrict__ hencT,
                                         float* __restrict__ pe, int tid) {
    if (tid < 400) {
        int j = tid % UNI, rq = tid / UNI;   // rows 2rq, 2rq+1
        float a0 = eb1[j], a1 = a0;
#pragma unroll
        for (int k = 0; k < LL; ++k) {
            float w = ew1[k * UNI + j];
            float2 yv = *(const float2*)(ytmpT + k * 8 + 2 * rq);
            a0 += yv.x * w; a1 += yv.y * w;
        }
        *(float2*)(hencT + j * 8 + 2 * rq) = make_float2(fast_tanh(a0), fast_tanh(a1));
    }
    __syncthreads();
    if (tid < 200) {
        int jj = tid % LL, ks = tid / LL;   // ks 0..9, K=10
        float a[8];
#pragma unroll
        for (int r = 0; r < 8; ++r) a[r] = 0.f;
#pragma unroll
        for (int k = ks * 10; k < ks * 10 + 10; ++k) {
            float w = ew2[k * LL + jj];
            float4 y0 = *(const float4*)(hencT + k * 8);
            float4 y1 = *(const float4*)(hencT + k * 8 + 4);
            a[0] += y0.x * w; a[1] += y0.y * w; a[2] += y0.z * w; a[3] += y0.w * w;
            a[4] += y1.x * w; a[5] += y1.y * w; a[6] += y1.z * w; a[7] += y1.w * w;
        }
        float* p = pe + ks * 160 + jj * 8;
        *(float4*)p       = make_float4(a[0], a[1], a[2], a[3]);
        *(float4*)(p + 4) = make_float4(a[4], a[5], a[6], a[7]);
    }
    __syncthreads();
}

#define ENC_K(tidv) (pe[(tidv)] + pe[160 + (tidv)] + pe[320 + (tidv)] + pe[480 + (tidv)] + \
                     pe[640 + (tidv)] + pe[800 + (tidv)] + pe[960 + (tidv)] + pe[1120 + (tidv)] + \
                     pe[1280 + (tidv)] + pe[1440 + (tidv)] + eb2[(tidv) >> 3])

// decoder MLP; l3 phase optionally absorbs the previous step's output projection
// (threads 320..447 project zproj -> out directly, full K=32, no partials)
__device__ __forceinline__ void dec_eval(const float* __restrict__ dw1,
                                         const float* __restrict__ db1,
                                         const float* __restrict__ dw2,
                                         const float* __restrict__ db2,
                                         const float* __restrict__ dw3,
                                         const float* __restrict__ zin,
                                         float* __restrict__ h1T,
                                         float* __restrict__ h2T,
                                         float* __restrict__ pd2,
                                         float* __restrict__ pd3, int tid,
                                         const float* __restrict__ ow,
                                         const float* __restrict__ ob,
                                         const float* __restrict__ zproj,
                                         float* __restrict__ outp,
                                         int b0, int pti) {
    if (tid < 400) {
        int j = tid % UNI, rq = tid / UNI;
        float a0 = db1[j], a1 = a0;
#pragma unroll 8
        for (int k = 0; k < LATD; ++k) {
            float w = dw1[k * UNI + j];
            float2 zv = *(const float2*)(zin + k * 8 + 2 * rq);
            a0 += zv.x * w; a1 += zv.y * w;
        }
        *(float2*)(h1T + j * 8 + 2 * rq) = make_float2(fast_tanh(a0), fast_tanh(a1));
    }
    __syncthreads();
    if (tid < 400) {
        int j = tid % UNI, ks = tid / UNI;   // ks 0..3, K=25
        float a[8];
#pragma unroll
        for (int r = 0; r < 8; ++r) a[r] = 0.f;
#pragma unroll 5
        for (int k = ks * 25; k < ks * 25 + 25; ++k) {
            float w = dw2[k * UNI + j];
            float4 z0 = *(const float4*)(h1T + k * 8);
            float4 z1 = *(const float4*)(h1T + k * 8 + 4);
            a[0] += z0.x * w; a[1] += z0.y * w; a[2] += z0.z * w; a[3] += z0.w * w;
            a[4] += z1.x * w; a[5] += z1.y * w; a[6] += z1.z * w; a[7] += z1.w * w;
        }
        float* p = pd2 + ks * 800 + j * 8;
        *(float4*)p       = make_float4(a[0], a[1], a[2], a[3]);
        *(float4*)(p + 4) = make_float4(a[4], a[5], a[6], a[7]);
    }
    __syncthreads();
    for (int i = tid; i < 800; i += NTHR)
        h2T[i] = fast_tanh(pd2[i] + pd2[800 + i] + pd2[1600 + i] + pd2[2400 + i] + db2[i >> 3]);
    __syncthreads();
    if (tid < 320) {
        int jj = tid % LATD, ks = tid / LATD;  // ks 0..9, K=10
        float a[8];
#pragma unroll
        for (int r = 0; r < 8; ++r) a[r] = 0.f;
#pragma unroll
        for (int k = ks * 10; k < ks * 10 + 10; ++k) {
            float w = dw3[k * LATD + jj];
            float4 z0 = *(const float4*)(h2T + k * 8);
            float4 z1 = *(const float4*)(h2T + k * 8 + 4);
            a[0] += z0.x * w; a[1] += z0.y * w; a[2] += z0.z * w; a[3] += z0.w * w;
            a[4] += z1.x * w; a[5] += z1.y * w; a[6] += z1.z * w; a[7] += z1.w * w;
        }
        float* p = pd3 + ks * 256 + jj * 8;
        *(float4*)p       = make_float4(a[0], a[1], a[2], a[3]);
        *(float4*)(p + 4) = make_float4(a[4], a[5], a[6], a[7]);
    } else if (tid < 448 && pti >= 0) {
        int d = tid - 320;
        float a[8];
        float b = ob[d];
#pragma unroll
        for (int r = 0; r < 8; ++r) a[r] = b;
#pragma unroll 8
        for (int k = 0; k < LATD; ++k) {
            float w = ow[k * DD + d];
            float4 z0 = *(const float4*)(zproj + k * 8);
            float4 z1 = *(const float4*)(zproj + k * 8 + 4);
            a[0] += z0.x * w; a[1] += z0.y * w; a[2] += z0.z * w; a[3] += z0.w * w;
            a[4] += z1.x * w; a[5] += z1.y * w; a[6] += z1.z * w; a[7] += z1.w * w;
        }
#pragma unroll
        for (int r = 0; r < 8; ++r)
            outp[(size_t)(b0 + r) * (TT * DD) + (size_t)pti * DD + d] = a[r];
    }
    __syncthreads();
}

#define DEC_K(tidv) (pd3[(tidv)] + pd3[256 + (tidv)] + pd3[512 + (tidv)] + pd3[768 + (tidv)] + \
                     pd3[1024 + (tidv)] + pd3[1280 + (tidv)] + pd3[1536 + (tidv)] + pd3[1792 + (tidv)] + \
                     pd3[2048 + (tidv)] + pd3[2304 + (tidv)] + db3[(tidv) >> 3])

extern "C" __global__ void __launch_bounds__(NTHR, 1)
latent_ode_main(const float* __restrict__ truth, const float* __restrict__ tarr,
                const int* __restrict__ obs_idx, const float* __restrict__ eps,
                const float* __restrict__ ew1g, const float* __restrict__ eb1g,
                const float* __restrict__ ew2g, const float* __restrict__ eb2g,
                const float* __restrict__ uw1, const float* __restrict__ ub1g,
                const float* __restrict__ uw2g, const float* __restrict__ ub2g,
                const float* __restrict__ rw1, const float* __restrict__ rb1g,
                const float* __restrict__ rw2g, const float* __restrict__ rb2g,
                const float* __restrict__ nw1, const float* __restrict__ nb1g,
                const float* __restrict__ nw2g, const float* __restrict__ nb2g,
                const float* __restrict__ z0w1, const float* __restrict__ z0b1,
                const float* __restrict__ z0w2, const float* __restrict__ z0b2,
                const float* __restrict__ dw1g, const float* __restrict__ db1g,
                const float* __restrict__ dw2g, const float* __restrict__ db2g,
                const float* __restrict__ dw3g, const float* __restrict__ db3g,
                const float* __restrict__ owg, const float* __restrict__ obg,
                float* __restrict__ out) {
    extern __shared__ float s[];
    const int tid = threadIdx.x;
    const int b0 = blockIdx.x * ROWS;

    float* zT = s;           // [32][8] k-major, persistent
    float* P  = s + 256;

    // ---------------- encoder smem layout ----------------
    float* ew1   = P;            // 2000
    float* ew2   = P + 2000;     // 2000
    float* eb1   = P + 4000;     // 100
    float* eb2   = P + 4100;     // 20 (pad to 4128)
    float* uw2   = P + 4128;     // 8000
    float* rw2   = P + 12128;    // 8000
    float* nw2   = P + 20128;    // 8000
    float* ub1   = P + 28128;    // 200
    float* rb1   = P + 28328;    // 200
    float* nb1   = P + 28528;    // 200
    float* ub2   = P + 28728;    // 40
    float* rb2   = P + 28768;    // 40
    float* nb2   = P + 28808;    // 40
    float* csu   = P + 28848;    // 200
    float* csr   = P + 29048;    // 200
    float* csn   = P + 29248;    // 200
    float* y     = P + 29448;    // 320  [8][40]
    float* ycT   = P + 29768;    // 1344 [168][8]; [0:160) doubles as ytmpT (ym k-major)
    float* accT  = P + 31272;    // 160
    float* hencT = P + 31432;    // 800
    float* pe    = P + 33832;    // 1600 [10][20][8]
    float* hTa   = P + 35432;    // 1600 [200][8]
    float* hTb   = P + 37032;    // 1600
    float* pL1   = P + 38632;    // 6400 [2 gates][2 ks][200][8]
    float* p2    = P + 45032;    // 2560 [2][4][40][8]
    float* pn    = P + 47592;    // 2560 [8][40][8]
    float* u_    = P + 50152;    // 320  [8][40]
    float* dts   = P + 50472;    // 140
    float* iob   = P + 50612;    // 140 (ints as bits)
    float* ddt   = P + 50752;    // 200 (outside decoder alias region -> persists)

    for (int i = tid; i < 2000; i += NTHR) { ew1[i] = ew1g[i]; ew2[i] = ew2g[i]; }
    for (int i = tid; i < 100;  i += NTHR) eb1[i] = eb1g[i];
    for (int i = tid; i < 20;   i += NTHR) eb2[i] = eb2g[i];
    for (int i = tid; i < 8000; i += NTHR) { uw2[i] = uw2g[i]; rw2[i] = rw2g[i]; nw2[i] = nw2g[i]; }
    for (int i = tid; i < 200;  i += NTHR) {
        ub1[i] = ub1g[i]; rb1[i] = rb1g[i]; nb1[i] = nb1g[i];
        csu[i] = g_colsum[i]; csr[i] = g_colsum[200 + i]; csn[i] = g_colsum[400 + i];
    }
    for (int i = tid; i < 40; i += NTHR) { ub2[i] = ub2g[i]; rb2[i] = rb2g[i]; nb2[i] = nb2g[i]; }
    for (int i = tid; i < ROWS * 40; i += NTHR) y[i] = 0.f;
    for (int i = tid; i < 320; i += NTHR) ycT[i] = 0.f;   // y-part (ym+ys) = 0
    for (int i = tid; i < TOBS; i += NTHR) {
        int io = obs_idx[TOBS - 1 - i];
        iob[i] = __int_as_float(io);
        dts[i] = (i > 0) ? (tarr[io] - tarr[obs_idx[TOBS - i]]) : 0.f;
    }
    for (int i = tid; i < TT - 1; i += NTHR) ddt[i] = tarr[i + 1] - tarr[i];
    __syncthreads();

    // ================= encoder scan =================
    for (int st = 0; st < TOBS; ++st) {
        int io = __float_as_int(iob[st]);
        float dt = dts[st];

        // ---- RK4 on ym (ycT[0:160) holds current ym, k-major) ----
        enc_eval(ew1, eb1, ew2, ycT, hencT, pe, tid);
        if (tid < 160) {
            int j = tid >> 3, r = tid & 7;
            float kv = ENC_K(tid);
            accT[tid] = kv;
            ycT[tid] = y[r * 40 + j] + 0.5f * dt * kv;
        } else {
            // truth prefetch into ycT x-part (k>=40): 352 threads, 1024 elems
            const float* trow = truth + (size_t)io * (BB * DD) + (size_t)b0 * DD;
            for (int i = tid - 160; i < 1024; i += 352) {
                int k = i >> 3, r = i & 7;
                ycT[(40 + k) * 8 + r] = trow[(size_t)r * DD + k];
            }
        }
        __syncthreads();
        enc_eval(ew1, eb1, ew2, ycT, hencT, pe, tid);
        if (tid < 160) {
            int j = tid >> 3, r = tid & 7;
            float kv = ENC_K(tid);
            accT[tid] += 2.f * kv;
            ycT[tid] = y[r * 40 + j] + 0.5f * dt * kv;
        }
        __syncthreads();
        enc_eval(ew1, eb1, ew2, ycT, hencT, pe, tid);
        if (tid < 160) {
            int j = tid >> 3, r = tid & 7;
            float kv = ENC_K(tid);
            accT[tid] += 2.f * kv;
            ycT[tid] = y[r * 40 + j] + dt * kv;
        }
        __syncthreads();
        enc_eval(ew1, eb1, ew2, ycT, hencT, pe, tid);
        if (tid < 160) {
            int j = tid >> 3, r = tid & 7;
            float kv = ENC_K(tid);
            float ynew = y[r * 40 + j] + dt * (1.f / 6.f) * (accT[tid] + kv);
            y[r * 40 + j] = ynew;
            ycT[tid] = ynew;            // final ym into ycT y-part
        }
        __syncthreads();

        // ---- u,r layer1 (K-split 2, 400 thr); ycT fully assembled ----
        if (tid < 400)
            gru_l1_dual_ks(uw1, rw1, ycT, pL1, pL1 + 3200, tid % GU, tid / GU);
        __syncthreads();
        // reduce + bias + tanh
        for (int i = tid; i < 3200; i += NTHR) {
            int g = i / 1600, rem = i % 1600, j = rem >> 3;
            float base = g ? (csr[j] + rb1[j]) : (csu[j] + ub1[j]);
            float v = pL1[g * 3200 + rem] + pL1[g * 3200 + 1600 + rem] + base;
            (g ? hTb : hTa)[rem] = fast_tanh(v);
        }
        __syncthreads();

        // ---- u,r layer2 (K-split 4, 320 thr) ----
        if (tid < 320) {
            int g = tid / 160, rem = tid % 160, jj = rem % 40, ks = rem / 40;  // K=50
            const float* hT = g ? hTb : hTa;
            const float* w2 = g ? rw2 : uw2;
            float a[8];
#pragma unroll
            for (int r = 0; r < 8; ++r) a[r] = 0.f;
#pragma unroll 10
            for (int k = ks * 50; k < ks * 50 + 50; ++k) {
                float w = w2[k * 40 + jj];
                float4 h0 = *(const float4*)(hT + k * 8);
                float4 h1 = *(const float4*)(hT + k * 8 + 4);
                a[0] += h0.x * w; a[1] += h0.y * w; a[2] += h0.z * w; a[3] += h0.w * w;
                a[4] += h1.x * w; a[5] += h1.y * w; a[6] += h1.z * w; a[7] += h1.w * w;
            }
            float* p = p2 + g * 1280 + ks * 320 + jj * 8;
            *(float4*)p       = make_float4(a[0], a[1], a[2], a[3]);
            *(float4*)(p + 4) = make_float4(a[4], a[5], a[6], a[7]);
        }
        __syncthreads();
        // reduce + sigmoid; g==1 (r gate) scales ycT in place, g==0 stores u_
        for (int i = tid; i < 640; i += NTHR) {
            int g = i / 320, rem = i % 320, jj = rem >> 3, r = rem & 7;
            const float* p = p2 + g * 1280;
            float a = p[rem] + p[320 + rem] + p[640 + rem] + p[960 + rem] + (g ? rb2 : ub2)[jj];
            float sg = fast_sigmoid(a);
            if (g) ycT[jj * 8 + r] *= sg;
            else   u_[r * 40 + jj] = sg;
        }
        __syncthreads();

        // ---- n layer1 (K-split 2, 400 thr; ycT already r-scaled) ----
        if (tid < 400)
            gru_l1_single_ks(nw1, ycT, pL1, tid % GU, tid / GU);
        __syncthreads();
        for (int i = tid; i < 1600; i += NTHR) {
            int j = i >> 3;
            hTa[i] = fast_tanh(pL1[i] + pL1[1600 + i] + csn[j] + nb1[j]);
        }
        __syncthreads();

        // ---- n layer2 (K-split 8, 320 thr) ----
        if (tid < 320) {
            int jj = tid % 40, ks = tid / 40;   // K=25
            float a[8];
#pragma unroll
            for (int r = 0; r < 8; ++r) a[r] = 0.f;
#pragma unroll 5
            for (int k = ks * 25; k < ks * 25 + 25; ++k) {
                float w = nw2[k * 40 + jj];
                float4 h0 = *(const float4*)(hTa + k * 8);
                float4 h1 = *(const float4*)(hTa + k * 8 + 4);
                a[0] += h0.x * w; a[1] += h0.y * w; a[2] += h0.z * w; a[3] += h0.w * w;
                a[4] += h1.x * w; a[5] += h1.y * w; a[6] += h1.z * w; a[7] += h1.w * w;
            }
            float* p = pn + ks * 320 + jj * 8;
            *(float4*)p       = make_float4(a[0], a[1], a[2], a[3]);
            *(float4*)(p + 4) = make_float4(a[4], a[5], a[6], a[7]);
        }
        __syncthreads();
        // reduce + state update; refresh full ycT y-part (ym+ys) for next step
        if (tid < 320) {
            int jj = tid >> 3, r = tid & 7;
            float a = pn[tid] + pn[320 + tid] + pn[640 + tid] + pn[960 + tid]
                    + pn[1280 + tid] + pn[1600 + tid] + pn[1920 + tid] + pn[2240 + tid] + nb2[jj];
            float val = (jj < LL) ? a : fabsf(a);
            float uu = u_[r * 40 + jj];
            float ynew = (1.f - uu) * val + uu * y[r * 40 + jj];
            y[r * 40 + jj] = ynew;
            ycT[jj * 8 + r] = ynew;
        }
        __syncthreads();
    }

    // ================= z0 head (once) =================
    for (int i = tid; i < ROWS * UNI; i += NTHR) {
        int r = i / UNI, j = i % UNI;
        float a = z0b1[j];
#pragma unroll 4
        for (int k = 0; k < 40; ++k) a += y[r * 40 + k] * z0w1[k * UNI + j];
        hencT[i] = fast_tanh(a);
    }
    __syncthreads();
    for (int i = tid; i < ROWS * 64; i += NTHR) {
        int r = i / 64, j = i % 64;
        float a = z0b2[j];
#pragma unroll 4
        for (int k = 0; k < UNI; ++k) a += hencT[r * UNI + k] * z0w2[k * 64 + j];
        hTa[r * 64 + j] = a;
    }
    __syncthreads();
    if (tid < 256) {
        int r = tid >> 5, j = tid & 31;
        float m = hTa[r * 64 + j];
        float sd = fabsf(hTa[r * 64 + 32 + j]);
        zT[j * 8 + r] = m + eps[(size_t)(b0 + r) * LATD + j] * sd;
    }
    __syncthreads();

    // ---------------- decoder smem layout (aliases P; ddt beyond -> safe) ----------------
    float* dw1   = P;             // 3200
    float* dw2   = P + 3200;      // 10000
    float* dw3   = P + 13200;     // 3200
    float* db1   = P + 16400;     // 100
    float* db2   = P + 16500;     // 100
    float* db3   = P + 16600;     // 32
    float* ow    = P + 16632;     // 4096
    float* ob    = P + 20728;     // 128
    float* h1T   = P + 20856;     // 800
    float* h2T   = P + 21656;     // 800
    float* ztmpT = P + 22456;     // 256
    float* zacc  = P + 22712;     // 256
    float* pd2   = P + 22968;     // 3200 [4][100][8]
    float* pd3   = P + 26168;     // 2560 [10][32][8]

    for (int i = tid; i < 3200;  i += NTHR) { dw1[i] = dw1g[i]; dw3[i] = dw3g[i]; }
    for (int i = tid; i < 10000; i += NTHR) dw2[i] = dw2g[i];
    for (int i = tid; i < 100;   i += NTHR) { db1[i] = db1g[i]; db2[i] = db2g[i]; }
    for (int i = tid; i < 32;    i += NTHR) db3[i] = db3g[i];
    for (int i = tid; i < 4096;  i += NTHR) ow[i] = owg[i];
    for (int i = tid; i < 128;   i += NTHR) ob[i] = obg[i];
    __syncthreads();

    // ================= decoder scan; projection(ti-1) absorbed in stage-1 l3 =================
    for (int ti = 1; ti < TT; ++ti) {
        float dt = ddt[ti - 1];
        // stage 1 reads zT; its l3 phase projects zT (== z at step ti-1) to out[ti-1]
        dec_eval(dw1, db1, dw2, db2, dw3, zT, h1T, h2T, pd2, pd3, tid,
                 ow, ob, zT, out, b0, ti - 1);
        if (tid < 256) {
            float kv = DEC_K(tid);
            zacc[tid] = kv;
            ztmpT[tid] = zT[tid] + 0.5f * dt * kv;
        }
        __syncthreads();
        dec_eval(dw1, db1, dw2, db2, dw3, ztmpT, h1T, h2T, pd2, pd3, tid,
                 ow, ob, zT, out, b0, -1);
        if (tid < 256) {
            float kv = DEC_K(tid);
            zacc[tid] += 2.f * kv;
            ztmpT[tid] = zT[tid] + 0.5f * dt * kv;
        }
        __syncthreads();
        dec_eval(dw1, db1, dw2, db2, dw3, ztmpT, h1T, h2T, pd2, pd3, tid,
                 ow, ob, zT, out, b0, -1);
        if (tid < 256) {
            float kv = DEC_K(tid);
            zacc[tid] += 2.f * kv;
            ztmpT[tid] = zT[tid] + dt * kv;
        }
        __syncthreads();
        dec_eval(dw1, db1, dw2, db2, dw3, ztmpT, h1T, h2T, pd2, pd3, tid,
                 ow, ob, zT, out, b0, -1);
        if (tid < 256) {
            float kv = DEC_K(tid);
            zT[tid] += dt * (1.f / 6.f) * (zacc[tid] + kv);
        }
        __syncthreads();
    }

    // final projection for ti = TT-1 (zT holds final z)
    if (tid < DD) {
        int d = tid;
        float a[8];
        float b = ob[d];
#pragma unroll
        for (int r = 0; r < 8; ++r) a[r] = b;
#pragma unroll 8
        for (int k = 0; k < LATD; ++k) {
            float w = ow[k * DD + d];
            float4 z0 = *(const float4*)(zT + k * 8);
            float4 z1 = *(const float4*)(zT + k * 8 + 4);
            a[0] += z0.x * w; a[1] += z0.y * w; a[2] += z0.z * w; a[3] += z0.w * w;
            a[4] += z1.x * w; a[5] += z1.y * w; a[6] += z1.z * w; a[7] += z1.w * w;
        }
#pragma unroll
        for (int r = 0; r < 8; ++r)
            out[(size_t)(b0 + r) * (TT * DD) + (size_t)(TT - 1) * DD + d] = a[r];
    }
}

extern "C" void kernel_launch(void* const* d_in, const int* in_sizes, int n_in,
                              void* d_out, int out_size) {
    (void)in_sizes; (void)n_in; (void)out_size;
    size_t smem = (size_t)SM_FLOATS * sizeof(float);
    cudaFuncSetAttribute(latent_ode_main, cudaFuncAttributeMaxDynamicSharedMemorySize, (int)smem);

    colsum_kernel<<<3, GU>>>((const float*)d_in[8], (const float*)d_in[12], (const float*)d_in[16]);

    latent_ode_main<<<NBLK, NTHR, smem>>>(
        (const float*)d_in[0], (const float*)d_in[1], (const int*)d_in[2], (const float*)d_in[3],
        (const float*)d_in[4],  (const float*)d_in[5],  (const float*)d_in[6],  (const float*)d_in[7],
        (const float*)d_in[8],  (const float*)d_in[9],  (const float*)d_in[10], (const float*)d_in[11],
        (const float*)d_in[12], (const float*)d_in[13], (const float*)d_in[14], (const float*)d_in[15],
        (const float*)d_in[16], (const float*)d_in[17], (const float*)d_in[18], (const float*)d_in[19],
        (const float*)d_in[20], (const float*)d_in[21], (const float*)d_in[22], (const float*)d_in[23],
        (const float*)d_in[24], (const float*)d_in[25], (const float*)d_in[26], (const float*)d_in[27],
        (const float*)d_in[28], (const float*)d_in[29], (const float*)d_in[30], (const float*)d_in[31],
        (float*)d_out);
}

// round 15
// speedup vs baseline: 1.8444x; 1.0304x over previous
#include <cuda_runtime.h>
#include <math.h>

#define TT   200
#define BB   1024
#define DD   128
#define TOBS 140
#define LL   20
#define LATD 32
#define GU   200
#define UNI  100
#define GIN  168      /* effective K: y(40)+x(128); ones-row folded into colsum */
#define ROWS 8
#define NTHR 512
#define NBLK (BB / ROWS)

#define KH   84       /* K per half for GRU l1 split-2 */

#define SM_FLOATS 51208

__device__ float g_colsum[3 * GU];

__device__ __forceinline__ float fast_tanh(float x) {
    float xc = fminf(fmaxf(x, -9.f), 9.f);
    float e = __expf(2.f * xc);
    return __fdividef(e - 1.f, e + 1.f);
}
__device__ __forceinline__ float fast_sigmoid(float x) {
    return __fdividef(1.f, 1.f + __expf(-x));
}

__global__ void colsum_kernel(const float* __restrict__ uw1,
                              const float* __restrict__ rw1,
                              const float* __restrict__ nw1) {
    int j = threadIdx.x;
    const float* w = (blockIdx.x == 0) ? uw1 : (blockIdx.x == 1 ? rw1 : nw1);
    float sacc = 0.f;
    for (int k = GIN; k < 2 * LL + 2 * DD; ++k) sacc += w[k * GU + j];
    g_colsum[blockIdx.x * GU + j] = sacc;
}

// ---- GRU layer1 dual (u,r): K-split 2, even/odd ping-pong prefetch (tiles of 6) ----
__device__ __forceinline__ void gru_l1_dual_ks(const float* __restrict__ wA,
                                               const float* __restrict__ wB,
                                               const float* __restrict__ ycT,
                                               float* __restrict__ pU,
                                               float* __restrict__ pR,
                                               int j, int ks) {
    float aA[8], aB[8];
#pragma unroll
    for (int r = 0; r < 8; ++r) { aA[r] = 0.f; aB[r] = 0.f; }
    const float* pA = wA + (size_t)ks * KH * GU + j;
    const float* pB = wB + (size_t)ks * KH * GU + j;
    const float* yc = ycT + ks * KH * 8;
    float wa0[6], wb0[6], wa1[6], wb1[6];
#pragma unroll
    for (int kk = 0; kk < 6; ++kk) { wa0[kk] = pA[kk * GU]; wb0[kk] = pB[kk * GU]; }
#pragma unroll 1
    for (int t = 0; t < 14; t += 2) {
#pragma unroll
        for (int kk = 0; kk < 6; ++kk) {
            wa1[kk] = pA[((t + 1) * 6 + kk) * GU];
            wb1[kk] = pB[((t + 1) * 6 + kk) * GU];
        }
#pragma unroll
        for (int kk = 0; kk < 6; ++kk) {
            int k = t * 6 + kk;
            float4 y0 = *(const float4*)(yc + k * 8);
            float4 y1 = *(const float4*)(yc + k * 8 + 4);
            float w0 = wa0[kk], w1 = wb0[kk];
            aA[0] += y0.x * w0; aA[1] += y0.y * w0; aA[2] += y0.z * w0; aA[3] += y0.w * w0;
            aA[4] += y1.x * w0; aA[5] += y1.y * w0; aA[6] += y1.z * w0; aA[7] += y1.w * w0;
            aB[0] += y0.x * w1; aB[1] += y0.y * w1; aB[2] += y0.z * w1; aB[3] += y0.w * w1;
            aB[4] += y1.x * w1; aB[5] += y1.y * w1; aB[6] += y1.z * w1; aB[7] += y1.w * w1;
        }
        if (t + 2 < 14) {
#pragma unroll
            for (int kk = 0; kk < 6; ++kk) {
                wa0[kk] = pA[((t + 2) * 6 + kk) * GU];
                wb0[kk] = pB[((t + 2) * 6 + kk) * GU];
            }
        }
#pragma unroll
        for (int kk = 0; kk < 6; ++kk) {
            int k = (t + 1) * 6 + kk;
            float4 y0 = *(const float4*)(yc + k * 8);
            float4 y1 = *(const float4*)(yc + k * 8 + 4);
            float w0 = wa1[kk], w1 = wb1[kk];
            aA[0] += y0.x * w0; aA[1] += y0.y * w0; aA[2] += y0.z * w0; aA[3] += y0.w * w0;
            aA[4] += y1.x * w0; aA[5] += y1.y * w0; aA[6] += y1.z * w0; aA[7] += y1.w * w0;
            aB[0] += y0.x * w1; aB[1] += y0.y * w1; aB[2] += y0.z * w1; aB[3] += y0.w * w1;
            aB[4] += y1.x * w1; aB[5] += y1.y * w1; aB[6] += y1.z * w1; aB[7] += y1.w * w1;
        }
    }
    float* u = pU + ks * 1600 + j * 8;
    float* rr = pR + ks * 1600 + j * 8;
    *(float4*)u        = make_float4(aA[0], aA[1], aA[2], aA[3]);
    *(float4*)(u + 4)  = make_float4(aA[4], aA[5], aA[6], aA[7]);
    *(float4*)rr       = make_float4(aB[0], aB[1], aB[2], aB[3]);
    *(float4*)(rr + 4) = make_float4(aB[4], aB[5], aB[6], aB[7]);
}

// ---- GRU n layer1: K-split 2, even/odd ping-pong prefetch (tiles of 12, 7 tiles) ----
__device__ __forceinline__ void gru_l1_single_ks(const float* __restrict__ wA,
                                                 const float* __restrict__ ycT,
                                                 float* __restrict__ pN,
                                                 int j, int ks) {
    float aA[8];
#pragma unroll
    for (int r = 0; r < 8; ++r) aA[r] = 0.f;
    const float* pA = wA + (size_t)ks * KH * GU + j;
    const float* yc = ycT + ks * KH * 8;
    float wa0[12], wa1[12];
#pragma unroll
    for (int kk = 0; kk < 12; ++kk) wa0[kk] = pA[kk * GU];
#pragma unroll 1
    for (int t = 0; t < 7; t += 2) {
        if (t + 1 < 7) {
#pragma unroll
            for (int kk = 0; kk < 12; ++kk) wa1[kk] = pA[((t + 1) * 12 + kk) * GU];
        }
#pragma unroll
        for (int kk = 0; kk < 12; ++kk) {
            int k = t * 12 + kk;
            float4 y0 = *(const float4*)(yc + k * 8);
            float4 y1 = *(const float4*)(yc + k * 8 + 4);
            float w0 = wa0[kk];
            aA[0] += y0.x * w0; aA[1] += y0.y * w0; aA[2] += y0.z * w0; aA[3] += y0.w * w0;
            aA[4] += y1.x * w0; aA[5] += y1.y * w0; aA[6] += y1.z * w0; aA[7] += y1.w * w0;
        }
        if (t + 2 < 7) {
#pragma unroll
            for (int kk = 0; kk < 12; ++kk) wa0[kk] = pA[((t + 2) * 12 + kk) * GU];
        }
        if (t + 1 < 7) {
#pragma unroll
            for (int kk = 0; kk < 12; ++kk) {
                int k = (t + 1) * 12 + kk;
                float4 y0 = *(const float4*)(yc + k * 8);
                float4 y1 = *(const float4*)(yc + k * 8 + 4);
                float w0 = wa1[kk];
                aA[0] += y0.x * w0; aA[1] += y0.y * w0; aA[2] += y0.z * w0; aA[3] += y0.w * w0;
                aA[4] += y1.x * w0; aA[5] += y1.y * w0; aA[6] += y1.z * w0; aA[7] += y1.w * w0;
            }
        }
    }
    float* p = pN + ks * 1600 + j * 8;
    *(float4*)p       = make_float4(aA[0], aA[1], aA[2], aA[3]);
    *(float4*)(p + 4) = make_float4(aA[4], aA[5], aA[6], aA[7]);
}

// encoder MLP: l1 direct (400 thr, 2 rows, no reduce), l2 partials (200 thr)
// ytmpT == ycT[0:160] (aliased, k-major ym)
__device__ __forceinline__ void enc_eval(const float* __restrict__ ew1,
                                         const float* __restrict__ eb1,
                                         const float* __restrict__ ew2,
                                         const float* __restrict__ ytmpT,
                                         float* __restrict__ hencT,
                                         float* __restrict__ pe, int tid) {
    if (tid < 400) {
        int j = tid % UNI, rq = tid / UNI;   // rows 2rq, 2rq+1
        float a0 = eb1[j], a1 = a0;
#pragma unroll
        for (int k = 0; k < LL; ++k) {
            float w = ew1[k * UNI + j];
            float2 yv = *(const float2*)(ytmpT + k * 8 + 2 * rq);
            a0 += yv.x * w; a1 += yv.y * w;
        }
        *(float2*)(hencT + j * 8 + 2 * rq) = make_float2(fast_tanh(a0), fast_tanh(a1));
    }
    __syncthreads();
    if (tid < 200) {
        int jj = tid % LL, ks = tid / LL;   // ks 0..9, K=10
        float a[8];
#pragma unroll
        for (int r = 0; r < 8; ++r) a[r] = 0.f;
#pragma unroll
        for (int k = ks * 10; k < ks * 10 + 10; ++k) {
            float w = ew2[k * LL + jj];
            float4 y0 = *(const float4*)(hencT + k * 8);
            float4 y1 = *(const float4*)(hencT + k * 8 + 4);
            a[0] += y0.x * w; a[1] += y0.y * w; a[2] += y0.z * w; a[3] += y0.w * w;
            a[4] += y1.x * w; a[5] += y1.y * w; a[6] += y1.z * w; a[7] += y1.w * w;
        }
        float* p = pe + ks * 160 + jj * 8;
        *(float4*)p       = make_float4(a[0], a[1], a[2], a[3]);
        *(float4*)(p + 4) = make_float4(a[4], a[5], a[6], a[7]);
    }
    __syncthreads();
}

#define ENC_K(tidv) (pe[(tidv)] + pe[160 + (tidv)] + pe[320 + (tidv)] + pe[480 + (tidv)] + \
                     pe[640 + (tidv)] + pe[800 + (tidv)] + pe[960 + (tidv)] + pe[1120 + (tidv)] + \
                     pe[1280 + (tidv)] + pe[1440 + (tidv)] + eb2[(tidv) >> 3])

// decoder MLP; l3 phase optionally absorbs the previous step's output projection
// (threads 320..447 project zproj -> out directly, full K=32, no partials)
__device__ __forceinline__ void dec_eval(const float* __restrict__ dw1,
                                         const float* __restrict__ db1,
                                         const float* __restrict__ dw2,
                                         const float* __restrict__ db2,
                                         const float* __restrict__ dw3,
                                         const float* __restrict__ zin,
                                         float* __restrict__ h1T,
                                         float* __restrict__ h2T,
                                         float* __restrict__ pd2,
                                         float* __restrict__ pd3, int tid,
                                         const float* __restrict__ ow,
                                         const float* __restrict__ ob,
                                         const float* __restrict__ zproj,
                                         float* __restrict__ outp,
                                         int b0, int pti) {
    if (tid < 400) {
        int j = tid % UNI, rq = tid / UNI;
        float a0 = db1[j], a1 = a0;
#pragma unroll 8
        for (int k = 0; k < LATD; ++k) {
            float w = dw1[k * UNI + j];
            float2 zv = *(const float2*)(zin + k * 8 + 2 * rq);
            a0 += zv.x * w; a1 += zv.y * w;
        }
        *(float2*)(h1T + j * 8 + 2 * rq) = make_float2(fast_tanh(a0), fast_tanh(a1));
    }
    __syncthreads();
    if (tid < 400) {
        int j = tid % UNI, ks = tid / UNI;   // ks 0..3, K=25
        float a[8];
#pragma unroll
        for (int r = 0; r < 8; ++r) a[r] = 0.f;
#pragma unroll 5
        for (int k = ks * 25; k < ks * 25 + 25; ++k) {
            float w = dw2[k * UNI + j];
            float4 z0 = *(const float4*)(h1T + k * 8);
            float4 z1 = *(const float4*)(h1T + k * 8 + 4);
            a[0] += z0.x * w; a[1] += z0.y * w; a[2] += z0.z * w; a[3] += z0.w * w;
            a[4] += z1.x * w; a[5] += z1.y * w; a[6] += z1.z * w; a[7] += z1.w * w;
        }
        float* p = pd2 + ks * 800 + j * 8;
        *(float4*)p       = make_float4(a[0], a[1], a[2], a[3]);
        *(float4*)(p + 4) = make_float4(a[4], a[5], a[6], a[7]);
    }
    __syncthreads();
    for (int i = tid; i < 800; i += NTHR)
        h2T[i] = fast_tanh(pd2[i] + pd2[800 + i] + pd2[1600 + i] + pd2[2400 + i] + db2[i >> 3]);
    __syncthreads();
    if (tid < 320) {
        int jj = tid % LATD, ks = tid / LATD;  // ks 0..9, K=10
        float a[8];
#pragma unroll
        for (int r = 0; r < 8; ++r) a[r] = 0.f;
#pragma unroll
        for (int k = ks * 10; k < ks * 10 + 10; ++k) {
            float w = dw3[k * LATD + jj];
            float4 z0 = *(const float4*)(h2T + k * 8);
            float4 z1 = *(const float4*)(h2T + k * 8 + 4);
            a[0] += z0.x * w; a[1] += z0.y * w; a[2] += z0.z * w; a[3] += z0.w * w;
            a[4] += z1.x * w; a[5] += z1.y * w; a[6] += z1.z * w; a[7] += z1.w * w;
        }
        float* p = pd3 + ks * 256 + jj * 8;
        *(float4*)p       = make_float4(a[0], a[1], a[2], a[3]);
        *(float4*)(p + 4) = make_float4(a[4], a[5], a[6], a[7]);
    } else if (tid < 448 && pti >= 0) {
        int d = tid - 320;
        float a[8];
        float b = ob[d];
#pragma unroll
        for (int r = 0; r < 8; ++r) a[r] = b;
#pragma unroll 8
        for (int k = 0; k < LATD; ++k) {
            float w = ow[k * DD + d];
            float4 z0 = *(const float4*)(zproj + k * 8);
            float4 z1 = *(const float4*)(zproj + k * 8 + 4);
            a[0] += z0.x * w; a[1] += z0.y * w; a[2] += z0.z * w; a[3] += z0.w * w;
            a[4] += z1.x * w; a[5] += z1.y * w; a[6] += z1.z * w; a[7] += z1.w * w;
        }
#pragma unroll
        for (int r = 0; r < 8; ++r)
            outp[(size_t)(b0 + r) * (TT * DD) + (size_t)pti * DD + d] = a[r];
    }
    __syncthreads();
}

#define DEC_K(tidv) (pd3[(tidv)] + pd3[256 + (tidv)] + pd3[512 + (tidv)] + pd3[768 + (tidv)] + \
                     pd3[1024 + (tidv)] + pd3[1280 + (tidv)] + pd3[1536 + (tidv)] + pd3[1792 + (tidv)] + \
                     pd3[2048 + (tidv)] + pd3[2304 + (tidv)] + db3[(tidv) >> 3])

extern "C" __global__ void __launch_bounds__(NTHR, 1)
latent_ode_main(const float* __restrict__ truth, const float* __restrict__ tarr,
                const int* __restrict__ obs_idx, const float* __restrict__ eps,
                const float* __restrict__ ew1g, const float* __restrict__ eb1g,
                const float* __restrict__ ew2g, const float* __restrict__ eb2g,
                const float* __restrict__ uw1, const float* __restrict__ ub1g,
                const float* __restrict__ uw2g, const float* __restrict__ ub2g,
                const float* __restrict__ rw1, const float* __restrict__ rb1g,
                const float* __restrict__ rw2g, const float* __restrict__ rb2g,
                const float* __restrict__ nw1, const float* __restrict__ nb1g,
                const float* __restrict__ nw2g, const float* __restrict__ nb2g,
                const float* __restrict__ z0w1, const float* __restrict__ z0b1,
                const float* __restrict__ z0w2, const float* __restrict__ z0b2,
                const float* __restrict__ dw1g, const float* __restrict__ db1g,
                const float* __restrict__ dw2g, const float* __restrict__ db2g,
                const float* __restrict__ dw3g, const float* __restrict__ db3g,
                const float* __restrict__ owg, const float* __restrict__ obg,
                float* __restrict__ out) {
    extern __shared__ float s[];
    const int tid = threadIdx.x;
    const int b0 = blockIdx.x * ROWS;

    float* zT = s;           // [32][8] k-major, persistent
    float* P  = s + 256;

    // ---------------- encoder smem layout ----------------
    float* ew1   = P;            // 2000
    float* ew2   = P + 2000;     // 2000
    float* eb1   = P + 4000;     // 100
    float* eb2   = P + 4100;     // 20 (pad to 4128)
    float* uw2   = P + 4128;     // 8000
    float* rw2   = P + 12128;    // 8000
    float* nw2   = P + 20128;    // 8000
    float* ub1   = P + 28128;    // 200
    float* rb1   = P + 28328;    // 200
    float* nb1   = P + 28528;    // 200
    float* ub2   = P + 28728;    // 40
    float* rb2   = P + 28768;    // 40
    float* nb2   = P + 28808;    // 40
    float* csu   = P + 28848;    // 200
    float* csr   = P + 29048;    // 200
    float* csn   = P + 29248;    // 200
    float* y     = P + 29448;    // 320  [8][40]
    float* ycT   = P + 29768;    // 1344 [168][8]; [0:160) doubles as ytmpT (ym k-major)
    float* accT  = P + 31272;    // 160
    float* hencT = P + 31432;    // 800
    float* pe    = P + 33832;    // 1600 [10][20][8]
    float* hTa   = P + 35432;    // 1600 [200][8]
    float* hTb   = P + 37032;    // 1600
    float* pL1   = P + 38632;    // 6400 [2 gates][2 ks][200][8]
    float* p2    = P + 45032;    // 2560 [2][4][40][8]
    float* pn    = P + 47592;    // 2560 [8][40][8]
    float* u_    = P + 50152;    // 320  [8][40]
    float* dts   = P + 50472;    // 140
    float* iob   = P + 50612;    // 140 (ints as bits)
    float* ddt   = P + 50752;    // 200 (outside decoder alias region -> persists)

    for (int i = tid; i < 2000; i += NTHR) { ew1[i] = ew1g[i]; ew2[i] = ew2g[i]; }
    for (int i = tid; i < 100;  i += NTHR) eb1[i] = eb1g[i];
    for (int i = tid; i < 20;   i += NTHR) eb2[i] = eb2g[i];
    for (int i = tid; i < 8000; i += NTHR) { uw2[i] = uw2g[i]; rw2[i] = rw2g[i]; nw2[i] = nw2g[i]; }
    for (int i = tid; i < 200;  i += NTHR) {
        ub1[i] = ub1g[i]; rb1[i] = rb1g[i]; nb1[i] = nb1g[i];
        csu[i] = g_colsum[i]; csr[i] = g_colsum[200 + i]; csn[i] = g_colsum[400 + i];
    }
    for (int i = tid; i < 40; i += NTHR) { ub2[i] = ub2g[i]; rb2[i] = rb2g[i]; nb2[i] = nb2g[i]; }
    for (int i = tid; i < ROWS * 40; i += NTHR) y[i] = 0.f;
    for (int i = tid; i < 320; i += NTHR) ycT[i] = 0.f;   // y-part (ym+ys) = 0
    for (int i = tid; i < TOBS; i += NTHR) {
        int io = obs_idx[TOBS - 1 - i];
        iob[i] = __int_as_float(io);
        dts[i] = (i > 0) ? (tarr[io] - tarr[obs_idx[TOBS - i]]) : 0.f;
    }
    for (int i = tid; i < TT - 1; i += NTHR) ddt[i] = tarr[i + 1] - tarr[i];
    __syncthreads();

    // ================= encoder scan =================
    for (int st = 0; st < TOBS; ++st) {
        int io = __float_as_int(iob[st]);
        float dt = dts[st];

        if (dt != 0.f) {
            // ---- RK4 on ym (ycT[0:160) holds current ym, k-major) ----
            enc_eval(ew1, eb1, ew2, ycT, hencT, pe, tid);
            if (tid < 160) {
                int j = tid >> 3, r = tid & 7;
                float kv = ENC_K(tid);
                accT[tid] = kv;
                ycT[tid] = y[r * 40 + j] + 0.5f * dt * kv;
            } else {
                // truth prefetch into ycT x-part (k>=40): 352 threads, 1024 elems
                const float* trow = truth + (size_t)io * (BB * DD) + (size_t)b0 * DD;
                for (int i = tid - 160; i < 1024; i += 352) {
                    int k = i >> 3, r = i & 7;
                    ycT[(40 + k) * 8 + r] = trow[(size_t)r * DD + k];
                }
            }
            __syncthreads();
            enc_eval(ew1, eb1, ew2, ycT, hencT, pe, tid);
            if (tid < 160) {
                int j = tid >> 3, r = tid & 7;
                float kv = ENC_K(tid);
                accT[tid] += 2.f * kv;
                ycT[tid] = y[r * 40 + j] + 0.5f * dt * kv;
            }
            __syncthreads();
            enc_eval(ew1, eb1, ew2, ycT, hencT, pe, tid);
            if (tid < 160) {
                int j = tid >> 3, r = tid & 7;
                float kv = ENC_K(tid);
                accT[tid] += 2.f * kv;
                ycT[tid] = y[r * 40 + j] + dt * kv;
            }
            __syncthreads();
            enc_eval(ew1, eb1, ew2, ycT, hencT, pe, tid);
            if (tid < 160) {
                int j = tid >> 3, r = tid & 7;
                float kv = ENC_K(tid);
                float ynew = y[r * 40 + j] + dt * (1.f / 6.f) * (accT[tid] + kv);
                y[r * 40 + j] = ynew;
                ycT[tid] = ynew;            // final ym into ycT y-part
            }
            __syncthreads();
        } else {
            // dt == 0: RK4 is an exact no-op (y + 0*k == y bitwise).
            // ycT y-part already holds y; just load this step's truth x-part.
            const float* trow = truth + (size_t)io * (BB * DD) + (size_t)b0 * DD;
            for (int i = tid; i < 1024; i += NTHR) {
                int k = i >> 3, r = i & 7;
                ycT[(40 + k) * 8 + r] = trow[(size_t)r * DD + k];
            }
            __syncthreads();
        }

        // ---- u,r layer1 (K-split 2, 400 thr); ycT fully assembled ----
        if (tid < 400)
            gru_l1_dual_ks(uw1, rw1, ycT, pL1, pL1 + 3200, tid % GU, tid / GU);
        __syncthreads();
        // reduce + bias + tanh
        for (int i = tid; i < 3200; i += NTHR) {
            int g = i / 1600, rem = i % 1600, j = rem >> 3;
            float base = g ? (csr[j] + rb1[j]) : (csu[j] + ub1[j]);
            float v = pL1[g * 3200 + rem] + pL1[g * 3200 + 1600 + rem] + base;
            (g ? hTb : hTa)[rem] = fast_tanh(v);
        }
        __syncthreads();

        // ---- u,r layer2 (K-split 4, 320 thr) ----
        if (tid < 320) {
            int g = tid / 160, rem = tid % 160, jj = rem % 40, ks = rem / 40;  // K=50
            const float* hT = g ? hTb : hTa;
            const float* w2 = g ? rw2 : uw2;
            float a[8];
#pragma unroll
            for (int r = 0; r < 8; ++r) a[r] = 0.f;
#pragma unroll 10
            for (int k = ks * 50; k < ks * 50 + 50; ++k) {
                float w = w2[k * 40 + jj];
                float4 h0 = *(const float4*)(hT + k * 8);
                float4 h1 = *(const float4*)(hT + k * 8 + 4);
                a[0] += h0.x * w; a[1] += h0.y * w; a[2] += h0.z * w; a[3] += h0.w * w;
                a[4] += h1.x * w; a[5] += h1.y * w; a[6] += h1.z * w; a[7] += h1.w * w;
            }
            float* p = p2 + g * 1280 + ks * 320 + jj * 8;
            *(float4*)p       = make_float4(a[0], a[1], a[2], a[3]);
            *(float4*)(p + 4) = make_float4(a[4], a[5], a[6], a[7]);
        }
        __syncthreads();
        // reduce + sigmoid; g==1 (r gate) scales ycT in place, g==0 stores u_
        for (int i = tid; i < 640; i += NTHR) {
            int g = i / 320, rem = i % 320, jj = rem >> 3, r = rem & 7;
            const float* p = p2 + g * 1280;
            float a = p[rem] + p[320 + rem] + p[640 + rem] + p[960 + rem] + (g ? rb2 : ub2)[jj];
            float sg = fast_sigmoid(a);
            if (g) ycT[jj * 8 + r] *= sg;
            else   u_[r * 40 + jj] = sg;
        }
        __syncthreads();

        // ---- n layer1 (K-split 2, 400 thr; ycT already r-scaled) ----
        if (tid < 400)
            gru_l1_single_ks(nw1, ycT, pL1, tid % GU, tid / GU);
        __syncthreads();
        for (int i = tid; i < 1600; i += NTHR) {
            int j = i >> 3;
            hTa[i] = fast_tanh(pL1[i] + pL1[1600 + i] + csn[j] + nb1[j]);
        }
        __syncthreads();

        // ---- n layer2 (K-split 8, 320 thr) ----
        if (tid < 320) {
            int jj = tid % 40, ks = tid / 40;   // K=25
            float a[8];
#pragma unroll
            for (int r = 0; r < 8; ++r) a[r] = 0.f;
#pragma unroll 5
            for (int k = ks * 25; k < ks * 25 + 25; ++k) {
                float w = nw2[k * 40 + jj];
                float4 h0 = *(const float4*)(hTa + k * 8);
                float4 h1 = *(const float4*)(hTa + k * 8 + 4);
                a[0] += h0.x * w; a[1] += h0.y * w; a[2] += h0.z * w; a[3] += h0.w * w;
                a[4] += h1.x * w; a[5] += h1.y * w; a[6] += h1.z * w; a[7] += h1.w * w;
            }
            float* p = pn + ks * 320 + jj * 8;
            *(float4*)p       = make_float4(a[0], a[1], a[2], a[3]);
            *(float4*)(p + 4) = make_float4(a[4], a[5], a[6], a[7]);
        }
        __syncthreads();
        // reduce + state update; refresh full ycT y-part (ym+ys) for next step
        if (tid < 320) {
            int jj = tid >> 3, r = tid & 7;
            float a = pn[tid] + pn[320 + tid] + pn[640 + tid] + pn[960 + tid]
                    + pn[1280 + tid] + pn[1600 + tid] + pn[1920 + tid] + pn[2240 + tid] + nb2[jj];
            float val = (jj < LL) ? a : fabsf(a);
            float uu = u_[r * 40 + jj];
            float ynew = (1.f - uu) * val + uu * y[r * 40 + jj];
            y[r * 40 + jj] = ynew;
            ycT[jj * 8 + r] = ynew;
        }
        __syncthreads();
    }

    // ================= z0 head (once) =================
    for (int i = tid; i < ROWS * UNI; i += NTHR) {
        int r = i / UNI, j = i % UNI;
        float a = z0b1[j];
#pragma unroll 4
        for (int k = 0; k < 40; ++k) a += y[r * 40 + k] * z0w1[k * UNI + j];
        hencT[i] = fast_tanh(a);
    }
    __syncthreads();
    for (int i = tid; i < ROWS * 64; i += NTHR) {
        int r = i / 64, j = i % 64;
        float a = z0b2[j];
#pragma unroll 4
        for (int k = 0; k < UNI; ++k) a += hencT[r * UNI + k] * z0w2[k * 64 + j];
        hTa[r * 64 + j] = a;
    }
    __syncthreads();
    if (tid < 256) {
        int r = tid >> 5, j = tid & 31;
        float m = hTa[r * 64 + j];
        float sd = fabsf(hTa[r * 64 + 32 + j]);
        zT[j * 8 + r] = m + eps[(size_t)(b0 + r) * LATD + j] * sd;
    }
    __syncthreads();

    // ---------------- decoder smem layout (aliases P; ddt beyond -> safe) ----------------
    float* dw1   = P;             // 3200
    float* dw2   = P + 3200;      // 10000
    float* dw3   = P + 13200;     // 3200
    float* db1   = P + 16400;     // 100
    float* db2   = P + 16500;     // 100
    float* db3   = P + 16600;     // 32
    float* ow    = P + 16632;     // 4096
    float* ob    = P + 20728;     // 128
    float* h1T   = P + 20856;     // 800
    float* h2T   = P + 21656;     // 800
    float* ztmpT = P + 22456;     // 256
    float* zacc  = P + 22712;     // 256
    float* pd2   = P + 22968;     // 3200 [4][100][8]
    float* pd3   = P + 26168;     // 2560 [10][32][8]

    for (int i = tid; i < 3200;  i += NTHR) { dw1[i] = dw1g[i]; dw3[i] = dw3g[i]; }
    for (int i = tid; i < 10000; i += NTHR) dw2[i] = dw2g[i];
    for (int i = tid; i < 100;   i += NTHR) { db1[i] = db1g[i]; db2[i] = db2g[i]; }
    for (int i = tid; i < 32;    i += NTHR) db3[i] = db3g[i];
    for (int i = tid; i < 4096;  i += NTHR) ow[i] = owg[i];
    for (int i = tid; i < 128;   i += NTHR) ob[i] = obg[i];
    __syncthreads();

    // ================= decoder scan; projection(ti-1) absorbed in stage-1 l3 =================
    for (int ti = 1; ti < TT; ++ti) {
        float dt = ddt[ti - 1];
        // stage 1 reads zT; its l3 phase projects zT (== z at step ti-1) to out[ti-1]
        dec_eval(dw1, db1, dw2, db2, dw3, zT, h1T, h2T, pd2, pd3, tid,
                 ow, ob, zT, out, b0, ti - 1);
        if (tid < 256) {
            float kv = DEC_K(tid);
            zacc[tid] = kv;
            ztmpT[tid] = zT[tid] + 0.5f * dt * kv;
        }
        __syncthreads();
        dec_eval(dw1, db1, dw2, db2, dw3, ztmpT, h1T, h2T, pd2, pd3, tid,
                 ow, ob, zT, out, b0, -1);
        if (tid < 256) {
            float kv = DEC_K(tid);
            zacc[tid] += 2.f * kv;
            ztmpT[tid] = zT[tid] + 0.5f * dt * kv;
        }
        __syncthreads();
        dec_eval(dw1, db1, dw2, db2, dw3, ztmpT, h1T, h2T, pd2, pd3, tid,
                 ow, ob, zT, out, b0, -1);
        if (tid < 256) {
            float kv = DEC_K(tid);
            zacc[tid] += 2.f * kv;
            ztmpT[tid] = zT[tid] + dt * kv;
        }
        __syncthreads();
        dec_eval(dw1, db1, dw2, db2, dw3, ztmpT, h1T, h2T, pd2, pd3, tid,
                 ow, ob, zT, out, b0, -1);
        if (tid < 256) {
            float kv = DEC_K(tid);
            zT[tid] += dt * (1.f / 6.f) * (zacc[tid] + kv);
        }
        __syncthreads();
    }

    // final projection for ti = TT-1 (zT holds final z)
    if (tid < DD) {
        int d = tid;
        float a[8];
        float b = ob[d];
#pragma unroll
        for (int r = 0; r < 8; ++r) a[r] = b;
#pragma unroll 8
        for (int k = 0; k < LATD; ++k) {
            float w = ow[k * DD + d];
            float4 z0 = *(const float4*)(zT + k * 8);
            float4 z1 = *(const float4*)(zT + k * 8 + 4);
            a[0] += z0.x * w; a[1] += z0.y * w; a[2] += z0.z * w; a[3] += z0.w * w;
            a[4] += z1.x * w; a[5] += z1.y * w; a[6] += z1.z * w; a[7] += z1.w * w;
        }
#pragma unroll
        for (int r = 0; r < 8; ++r)
            out[(size_t)(b0 + r) * (TT * DD) + (size_t)(TT - 1) * DD + d] = a[r];
    }
}

extern "C" void kernel_launch(void* const* d_in, const int* in_sizes, int n_in,
                              void* d_out, int out_size) {
    (void)in_sizes; (void)n_in; (void)out_size;
    size_t smem = (size_t)SM_FLOATS * sizeof(float);
    cudaFuncSetAttribute(latent_ode_main, cudaFuncAttributeMaxDynamicSharedMemorySize, (int)smem);

    colsum_kernel<<<3, GU>>>((const float*)d_in[8], (const float*)d_in[12], (const float*)d_in[16]);

    latent_ode_main<<<NBLK, NTHR, smem>>>(
        (const float*)d_in[0], (const float*)d_in[1], (const int*)d_in[2], (const float*)d_in[3],
        (const float*)d_in[4],  (const float*)d_in[5],  (const float*)d_in[6],  (const float*)d_in[7],
        (const float*)d_in[8],  (const float*)d_in[9],  (const float*)d_in[10], (const float*)d_in[11],
        (const float*)d_in[12], (const float*)d_in[13], (const float*)d_in[14], (const float*)d_in[15],
        (const float*)d_in[16], (const float*)d_in[17], (const float*)d_in[18], (const float*)d_in[19],
        (const float*)d_in[20], (const float*)d_in[21], (const float*)d_in[22], (const float*)d_in[23],
        (const float*)d_in[24], (const float*)d_in[25], (const float*)d_in[26], (const float*)d_in[27],
        (const float*)d_in[28], (const float*)d_in[29], (const float*)d_in[30], (const float*)d_in[31],
        (float*)d_out);
}

// round 16
// speedup vs baseline: 1.8949x; 1.0274x over previous
#include <cuda_runtime.h>
#include <math.h>

#define TT   200
#define BB   1024
#define DD   128
#define TOBS 140
#define LL   20
#define LATD 32
#define GU   200
#define UNI  100
#define GIN  168      /* effective K: y(40)+x(128); ones-row folded into colsum */
#define ROWS 8
#define NTHR 768
#define NBLK (BB / ROWS)

#define KS3  56       /* K per split for GRU l1 split-3 */

#define SM_FLOATS 54408

__device__ float g_colsum[3 * GU];

__device__ __forceinline__ float fast_tanh(float x) {
    float xc = fminf(fmaxf(x, -9.f), 9.f);
    float e = __expf(2.f * xc);
    return __fdividef(e - 1.f, e + 1.f);
}
__device__ __forceinline__ float fast_sigmoid(float x) {
    return __fdividef(1.f, 1.f + __expf(-x));
}

__global__ void colsum_kernel(const float* __restrict__ uw1,
                              const float* __restrict__ rw1,
                              const float* __restrict__ nw1) {
    int j = threadIdx.x;
    const float* w = (blockIdx.x == 0) ? uw1 : (blockIdx.x == 1 ? rw1 : nw1);
    float sacc = 0.f;
    for (int k = GIN; k < 2 * LL + 2 * DD; ++k) sacc += w[k * GU + j];
    g_colsum[blockIdx.x * GU + j] = sacc;
}

// ---- GRU layer1 dual (u,r): K-split 3, even/odd ping-pong prefetch (8 tiles of 7) ----
__device__ __forceinline__ void gru_l1_dual_ks(const float* __restrict__ wA,
                                               const float* __restrict__ wB,
                                               const float* __restrict__ ycT,
                                               float* __restrict__ pU,
                                               float* __restrict__ pR,
                                               int j, int ks) {
    float aA[8], aB[8];
#pragma unroll
    for (int r = 0; r < 8; ++r) { aA[r] = 0.f; aB[r] = 0.f; }
    const float* pA = wA + (size_t)ks * KS3 * GU + j;
    const float* pB = wB + (size_t)ks * KS3 * GU + j;
    const float* yc = ycT + ks * KS3 * 8;
    float wa0[7], wb0[7], wa1[7], wb1[7];
#pragma unroll
    for (int kk = 0; kk < 7; ++kk) { wa0[kk] = pA[kk * GU]; wb0[kk] = pB[kk * GU]; }
#pragma unroll 1
    for (int t = 0; t < 8; t += 2) {
#pragma unroll
        for (int kk = 0; kk < 7; ++kk) {
            wa1[kk] = pA[((t + 1) * 7 + kk) * GU];
            wb1[kk] = pB[((t + 1) * 7 + kk) * GU];
        }
#pragma unroll
        for (int kk = 0; kk < 7; ++kk) {
            int k = t * 7 + kk;
            float4 y0 = *(const float4*)(yc + k * 8);
            float4 y1 = *(const float4*)(yc + k * 8 + 4);
            float w0 = wa0[kk], w1 = wb0[kk];
            aA[0] += y0.x * w0; aA[1] += y0.y * w0; aA[2] += y0.z * w0; aA[3] += y0.w * w0;
            aA[4] += y1.x * w0; aA[5] += y1.y * w0; aA[6] += y1.z * w0; aA[7] += y1.w * w0;
            aB[0] += y0.x * w1; aB[1] += y0.y * w1; aB[2] += y0.z * w1; aB[3] += y0.w * w1;
            aB[4] += y1.x * w1; aB[5] += y1.y * w1; aB[6] += y1.z * w1; aB[7] += y1.w * w1;
        }
        if (t + 2 < 8) {
#pragma unroll
            for (int kk = 0; kk < 7; ++kk) {
                wa0[kk] = pA[((t + 2) * 7 + kk) * GU];
                wb0[kk] = pB[((t + 2) * 7 + kk) * GU];
            }
        }
#pragma unroll
        for (int kk = 0; kk < 7; ++kk) {
            int k = (t + 1) * 7 + kk;
            float4 y0 = *(const float4*)(yc + k * 8);
            float4 y1 = *(const float4*)(yc + k * 8 + 4);
            float w0 = wa1[kk], w1 = wb1[kk];
            aA[0] += y0.x * w0; aA[1] += y0.y * w0; aA[2] += y0.z * w0; aA[3] += y0.w * w0;
            aA[4] += y1.x * w0; aA[5] += y1.y * w0; aA[6] += y1.z * w0; aA[7] += y1.w * w0;
            aB[0] += y0.x * w1; aB[1] += y0.y * w1; aB[2] += y0.z * w1; aB[3] += y0.w * w1;
            aB[4] += y1.x * w1; aB[5] += y1.y * w1; aB[6] += y1.z * w1; aB[7] += y1.w * w1;
        }
    }
    float* u = pU + ks * 1600 + j * 8;
    float* rr = pR + ks * 1600 + j * 8;
    *(float4*)u        = make_float4(aA[0], aA[1], aA[2], aA[3]);
    *(float4*)(u + 4)  = make_float4(aA[4], aA[5], aA[6], aA[7]);
    *(float4*)rr       = make_float4(aB[0], aB[1], aB[2], aB[3]);
    *(float4*)(rr + 4) = make_float4(aB[4], aB[5], aB[6], aB[7]);
}

// ---- GRU n layer1: K-split 3, even/odd ping-pong prefetch (7 tiles of 8) ----
__device__ __forceinline__ void gru_l1_single_ks(const float* __restrict__ wA,
                                                 const float* __restrict__ ycT,
                                                 float* __restrict__ pN,
                                                 int j, int ks) {
    float aA[8];
#pragma unroll
    for (int r = 0; r < 8; ++r) aA[r] = 0.f;
    const float* pA = wA + (size_t)ks * KS3 * GU + j;
    const float* yc = ycT + ks * KS3 * 8;
    float wa0[8], wa1[8];
#pragma unroll
    for (int kk = 0; kk < 8; ++kk) wa0[kk] = pA[kk * GU];
#pragma unroll 1
    for (int t = 0; t < 7; t += 2) {
        if (t + 1 < 7) {
#pragma unroll
            for (int kk = 0; kk < 8; ++kk) wa1[kk] = pA[((t + 1) * 8 + kk) * GU];
        }
#pragma unroll
        for (int kk = 0; kk < 8; ++kk) {
            int k = t * 8 + kk;
            float4 y0 = *(const float4*)(yc + k * 8);
            float4 y1 = *(const float4*)(yc + k * 8 + 4);
            float w0 = wa0[kk];
            aA[0] += y0.x * w0; aA[1] += y0.y * w0; aA[2] += y0.z * w0; aA[3] += y0.w * w0;
            aA[4] += y1.x * w0; aA[5] += y1.y * w0; aA[6] += y1.z * w0; aA[7] += y1.w * w0;
        }
        if (t + 2 < 7) {
#pragma unroll
            for (int kk = 0; kk < 8; ++kk) wa0[kk] = pA[((t + 2) * 8 + kk) * GU];
        }
        if (t + 1 < 7) {
#pragma unroll
            for (int kk = 0; kk < 8; ++kk) {
                int k = (t + 1) * 8 + kk;
                float4 y0 = *(const float4*)(yc + k * 8);
                float4 y1 = *(const float4*)(yc + k * 8 + 4);
                float w0 = wa1[kk];
                aA[0] += y0.x * w0; aA[1] += y0.y * w0; aA[2] += y0.z * w0; aA[3] += y0.w * w0;
                aA[4] += y1.x * w0; aA[5] += y1.y * w0; aA[6] += y1.z * w0; aA[7] += y1.w * w0;
            }
        }
    }
    float* p = pN + ks * 1600 + j * 8;
    *(float4*)p       = make_float4(aA[0], aA[1], aA[2], aA[3]);
    *(float4*)(p + 4) = make_float4(aA[4], aA[5], aA[6], aA[7]);
}

// encoder MLP: l1 direct (400 thr, 2 rows, no reduce), l2 partials (200 thr)
__device__ __forceinline__ void enc_eval(const float* __restrict__ ew1,
                                         const float* __restrict__ eb1,
                                         const float* __restrict__ ew2,
                                         const float* __restrict__ ytmpT,
                                         float* __restrict__ hencT,
                                         float* __restrict__ pe, int tid) {
    if (tid < 400) {
        int j = tid % UNI, rq = tid / UNI;   // rows 2rq, 2rq+1
        float a0 = eb1[j], a1 = a0;
#pragma unroll
        for (int k = 0; k < LL; ++k) {
            float w = ew1[k * UNI + j];
            float2 yv = *(const float2*)(ytmpT + k * 8 + 2 * rq);
            a0 += yv.x * w; a1 += yv.y * w;
        }
        *(float2*)(hencT + j * 8 + 2 * rq) = make_float2(fast_tanh(a0), fast_tanh(a1));
    }
    __syncthreads();
    if (tid < 200) {
        int jj = tid % LL, ks = tid / LL;   // ks 0..9, K=10
        float a[8];
#pragma unroll
        for (int r = 0; r < 8; ++r) a[r] = 0.f;
#pragma unroll
        for (int k = ks * 10; k < ks * 10 + 10; ++k) {
            float w = ew2[k * LL + jj];
            float4 y0 = *(const float4*)(hencT + k * 8);
            float4 y1 = *(const float4*)(hencT + k * 8 + 4);
            a[0] += y0.x * w; a[1] += y0.y * w; a[2] += y0.z * w; a[3] += y0.w * w;
            a[4] += y1.x * w; a[5] += y1.y * w; a[6] += y1.z * w; a[7] += y1.w * w;
        }
        float* p = pe + ks * 160 + jj * 8;
        *(float4*)p       = make_float4(a[0], a[1], a[2], a[3]);
        *(float4*)(p + 4) = make_float4(a[4], a[5], a[6], a[7]);
    }
    __syncthreads();
}

#define ENC_K(tidv) (pe[(tidv)] + pe[160 + (tidv)] + pe[320 + (tidv)] + pe[480 + (tidv)] + \
                     pe[640 + (tidv)] + pe[800 + (tidv)] + pe[960 + (tidv)] + pe[1120 + (tidv)] + \
                     pe[1280 + (tidv)] + pe[1440 + (tidv)] + eb2[(tidv) >> 3])

// decoder MLP; l3 phase optionally absorbs the previous step's output projection
__device__ __forceinline__ void dec_eval(const float* __restrict__ dw1,
                                         const float* __restrict__ db1,
                                         const float* __restrict__ dw2,
                                         const float* __restrict__ db2,
                                         const float* __restrict__ dw3,
                                         const float* __restrict__ zin,
                                         float* __restrict__ h1T,
                                         float* __restrict__ h2T,
                                         float* __restrict__ pd2,
                                         float* __restrict__ pd3, int tid,
                                         const float* __restrict__ ow,
                                         const float* __restrict__ ob,
                                         const float* __restrict__ zproj,
                                         float* __restrict__ outp,
                                         int b0, int pti) {
    if (tid < 400) {
        int j = tid % UNI, rq = tid / UNI;
        float a0 = db1[j], a1 = a0;
#pragma unroll 8
        for (int k = 0; k < LATD; ++k) {
            float w = dw1[k * UNI + j];
            float2 zv = *(const float2*)(zin + k * 8 + 2 * rq);
            a0 += zv.x * w; a1 += zv.y * w;
        }
        *(float2*)(h1T + j * 8 + 2 * rq) = make_float2(fast_tanh(a0), fast_tanh(a1));
    }
    __syncthreads();
    if (tid < 400) {
        int j = tid % UNI, ks = tid / UNI;   // ks 0..3, K=25
        float a[8];
#pragma unroll
        for (int r = 0; r < 8; ++r) a[r] = 0.f;
#pragma unroll 5
        for (int k = ks * 25; k < ks * 25 + 25; ++k) {
            float w = dw2[k * UNI + j];
            float4 z0 = *(const float4*)(h1T + k * 8);
            float4 z1 = *(const float4*)(h1T + k * 8 + 4);
            a[0] += z0.x * w; a[1] += z0.y * w; a[2] += z0.z * w; a[3] += z0.w * w;
            a[4] += z1.x * w; a[5] += z1.y * w; a[6] += z1.z * w; a[7] += z1.w * w;
        }
        float* p = pd2 + ks * 800 + j * 8;
        *(float4*)p       = make_float4(a[0], a[1], a[2], a[3]);
        *(float4*)(p + 4) = make_float4(a[4], a[5], a[6], a[7]);
    }
    __syncthreads();
    for (int i = tid; i < 800; i += NTHR)
        h2T[i] = fast_tanh(pd2[i] + pd2[800 + i] + pd2[1600 + i] + pd2[2400 + i] + db2[i >> 3]);
    __syncthreads();
    if (tid < 320) {
        int jj = tid % LATD, ks = tid / LATD;  // ks 0..9, K=10
        float a[8];
#pragma unroll
        for (int r = 0; r < 8; ++r) a[r] = 0.f;
#pragma unroll
        for (int k = ks * 10; k < ks * 10 + 10; ++k) {
            float w = dw3[k * LATD + jj];
            float4 z0 = *(const float4*)(h2T + k * 8);
            float4 z1 = *(const float4*)(h2T + k * 8 + 4);
            a[0] += z0.x * w; a[1] += z0.y * w; a[2] += z0.z * w; a[3] += z0.w * w;
            a[4] += z1.x * w; a[5] += z1.y * w; a[6] += z1.z * w; a[7] += z1.w * w;
        }
        float* p = pd3 + ks * 256 + jj * 8;
        *(float4*)p       = make_float4(a[0], a[1], a[2], a[3]);
        *(float4*)(p + 4) = make_float4(a[4], a[5], a[6], a[7]);
    } else if (tid < 448 && pti >= 0) {
        int d = tid - 320;
        float a[8];
        float b = ob[d];
#pragma unroll
        for (int r = 0; r < 8; ++r) a[r] = b;
#pragma unroll 8
        for (int k = 0; k < LATD; ++k) {
            float w = ow[k * DD + d];
            float4 z0 = *(const float4*)(zproj + k * 8);
            float4 z1 = *(const float4*)(zproj + k * 8 + 4);
            a[0] += z0.x * w; a[1] += z0.y * w; a[2] += z0.z * w; a[3] += z0.w * w;
            a[4] += z1.x * w; a[5] += z1.y * w; a[6] += z1.z * w; a[7] += z1.w * w;
        }
#pragma unroll
        for (int r = 0; r < 8; ++r)
            outp[(size_t)(b0 + r) * (TT * DD) + (size_t)pti * DD + d] = a[r];
    }
    __syncthreads();
}

#define DEC_K(tidv) (pd3[(tidv)] + pd3[256 + (tidv)] + pd3[512 + (tidv)] + pd3[768 + (tidv)] + \
                     pd3[1024 + (tidv)] + pd3[1280 + (tidv)] + pd3[1536 + (tidv)] + pd3[1792 + (tidv)] + \
                     pd3[2048 + (tidv)] + pd3[2304 + (tidv)] + db3[(tidv) >> 3])

extern "C" __global__ void __launch_bounds__(NTHR, 1)
latent_ode_main(const float* __restrict__ truth, const float* __restrict__ tarr,
                const int* __restrict__ obs_idx, const float* __restrict__ eps,
                const float* __restrict__ ew1g, const float* __restrict__ eb1g,
                const float* __restrict__ ew2g, const float* __restrict__ eb2g,
                const float* __restrict__ uw1, const float* __restrict__ ub1g,
                const float* __restrict__ uw2g, const float* __restrict__ ub2g,
                const float* __restrict__ rw1, const float* __restrict__ rb1g,
                const float* __restrict__ rw2g, const float* __restrict__ rb2g,
                const float* __restrict__ nw1, const float* __restrict__ nb1g,
                const float* __restrict__ nw2g, const float* __restrict__ nb2g,
                const float* __restrict__ z0w1, const float* __restrict__ z0b1,
                const float* __restrict__ z0w2, const float* __restrict__ z0b2,
                const float* __restrict__ dw1g, const float* __restrict__ db1g,
                const float* __restrict__ dw2g, const float* __restrict__ db2g,
                const float* __restrict__ dw3g, const float* __restrict__ db3g,
                const float* __restrict__ owg, const float* __restrict__ obg,
                float* __restrict__ out) {
    extern __shared__ float s[];
    const int tid = threadIdx.x;
    const int b0 = blockIdx.x * ROWS;

    float* zT = s;           // [32][8] k-major, persistent
    float* P  = s + 256;

    // ---------------- encoder smem layout ----------------
    float* ew1   = P;            // 2000
    float* ew2   = P + 2000;     // 2000
    float* eb1   = P + 4000;     // 100
    float* eb2   = P + 4100;     // 20 (pad to 4128)
    float* uw2   = P + 4128;     // 8000
    float* rw2   = P + 12128;    // 8000
    float* nw2   = P + 20128;    // 8000
    float* ub1   = P + 28128;    // 200
    float* rb1   = P + 28328;    // 200
    float* nb1   = P + 28528;    // 200
    float* ub2   = P + 28728;    // 40
    float* rb2   = P + 28768;    // 40
    float* nb2   = P + 28808;    // 40
    float* csu   = P + 28848;    // 200
    float* csr   = P + 29048;    // 200
    float* csn   = P + 29248;    // 200
    float* y     = P + 29448;    // 320  [8][40]
    float* ycT   = P + 29768;    // 1344 [168][8]; [0:160) doubles as ytmpT (ym k-major)
    float* accT  = P + 31272;    // 160
    float* hencT = P + 31432;    // 800
    float* pe    = P + 33832;    // 1600 [10][20][8]
    float* hTa   = P + 35432;    // 1600 [200][8]
    float* hTb   = P + 37032;    // 1600
    float* pL1   = P + 38632;    // 9600 [2 gates][3 ks][200][8]
    float* p2    = P + 48232;    // 2560 [2][4][40][8]
    float* pn    = P + 50792;    // 2560 [8][40][8]
    float* u_    = P + 53352;    // 320  [8][40]
    float* dts   = P + 53672;    // 140
    float* iob   = P + 53812;    // 140 (ints as bits)
    float* ddt   = P + 53952;    // 200 (outside decoder alias region -> persists)

    for (int i = tid; i < 2000; i += NTHR) { ew1[i] = ew1g[i]; ew2[i] = ew2g[i]; }
    for (int i = tid; i < 100;  i += NTHR) eb1[i] = eb1g[i];
    for (int i = tid; i < 20;   i += NTHR) eb2[i] = eb2g[i];
    for (int i = tid; i < 8000; i += NTHR) { uw2[i] = uw2g[i]; rw2[i] = rw2g[i]; nw2[i] = nw2g[i]; }
    for (int i = tid; i < 200;  i += NTHR) {
        ub1[i] = ub1g[i]; rb1[i] = rb1g[i]; nb1[i] = nb1g[i];
        csu[i] = g_colsum[i]; csr[i] = g_colsum[200 + i]; csn[i] = g_colsum[400 + i];
    }
    for (int i = tid; i < 40; i += NTHR) { ub2[i] = ub2g[i]; rb2[i] = rb2g[i]; nb2[i] = nb2g[i]; }
    for (int i = tid; i < ROWS * 40; i += NTHR) y[i] = 0.f;
    for (int i = tid; i < 320; i += NTHR) ycT[i] = 0.f;   // y-part (ym+ys) = 0
    for (int i = tid; i < TOBS; i += NTHR) {
        int io = obs_idx[TOBS - 1 - i];
        iob[i] = __int_as_float(io);
        dts[i] = (i > 0) ? (tarr[io] - tarr[obs_idx[TOBS - i]]) : 0.f;
    }
    for (int i = tid; i < TT - 1; i += NTHR) ddt[i] = tarr[i + 1] - tarr[i];
    __syncthreads();

    // ================= encoder scan =================
    for (int st = 0; st < TOBS; ++st) {
        int io = __float_as_int(iob[st]);
        float dt = dts[st];

        if (dt != 0.f) {
            // ---- RK4 on ym (ycT[0:160) holds current ym, k-major) ----
            enc_eval(ew1, eb1, ew2, ycT, hencT, pe, tid);
            if (tid < 160) {
                int j = tid >> 3, r = tid & 7;
                float kv = ENC_K(tid);
                accT[tid] = kv;
                ycT[tid] = y[r * 40 + j] + 0.5f * dt * kv;
            } else {
                // truth prefetch into ycT x-part (k>=40): 608 threads, 1024 elems
                const float* trow = truth + (size_t)io * (BB * DD) + (size_t)b0 * DD;
                for (int i = tid - 160; i < 1024; i += NTHR - 160) {
                    int k = i >> 3, r = i & 7;
                    ycT[(40 + k) * 8 + r] = trow[(size_t)r * DD + k];
                }
            }
            __syncthreads();
            enc_eval(ew1, eb1, ew2, ycT, hencT, pe, tid);
            if (tid < 160) {
                int j = tid >> 3, r = tid & 7;
                float kv = ENC_K(tid);
                accT[tid] += 2.f * kv;
                ycT[tid] = y[r * 40 + j] + 0.5f * dt * kv;
            }
            __syncthreads();
            enc_eval(ew1, eb1, ew2, ycT, hencT, pe, tid);
            if (tid < 160) {
                int j = tid >> 3, r = tid & 7;
                float kv = ENC_K(tid);
                accT[tid] += 2.f * kv;
                ycT[tid] = y[r * 40 + j] + dt * kv;
            }
            __syncthreads();
            enc_eval(ew1, eb1, ew2, ycT, hencT, pe, tid);
            if (tid < 160) {
                int j = tid >> 3, r = tid & 7;
                float kv = ENC_K(tid);
                float ynew = y[r * 40 + j] + dt * (1.f / 6.f) * (accT[tid] + kv);
                y[r * 40 + j] = ynew;
                ycT[tid] = ynew;            // final ym into ycT y-part
            }
            __syncthreads();
        } else if (st == 0) {
            // first step: load truth x-part once (dt==0 so RK4 is a no-op)
            const float* trow = truth + (size_t)io * (BB * DD) + (size_t)b0 * DD;
            for (int i = tid; i < 1024; i += NTHR) {
                int k = i >> 3, r = i & 7;
                ycT[(40 + k) * 8 + r] = trow[(size_t)r * DD + k];
            }
            __syncthreads();
        }
        // dt==0 && st>0: duplicate obs (same io) -> RK4 no-op AND ycT x-part
        // already holds truth[io] (GRU never touches k>=40). Fall straight through.

        // ---- u,r layer1 (K-split 3, 600 thr); ycT fully assembled ----
        if (tid < 600)
            gru_l1_dual_ks(uw1, rw1, ycT, pL1, pL1 + 4800, tid % GU, tid / GU);
        __syncthreads();
        // reduce + bias + tanh (3 partials)
        for (int i = tid; i < 3200; i += NTHR) {
            int g = i / 1600, rem = i % 1600, j = rem >> 3;
            float base = g ? (csr[j] + rb1[j]) : (csu[j] + ub1[j]);
            const float* p = pL1 + g * 4800;
            float v = p[rem] + p[1600 + rem] + p[3200 + rem] + base;
            (g ? hTb : hTa)[rem] = fast_tanh(v);
        }
        __syncthreads();

        // ---- u,r layer2 (K-split 4, 320 thr) ----
        if (tid < 320) {
            int g = tid / 160, rem = tid % 160, jj = rem % 40, ks = rem / 40;  // K=50
            const float* hT = g ? hTb : hTa;
            const float* w2 = g ? rw2 : uw2;
            float a[8];
#pragma unroll
            for (int r = 0; r < 8; ++r) a[r] = 0.f;
#pragma unroll 10
            for (int k = ks * 50; k < ks * 50 + 50; ++k) {
                float w = w2[k * 40 + jj];
                float4 h0 = *(const float4*)(hT + k * 8);
                float4 h1 = *(const float4*)(hT + k * 8 + 4);
                a[0] += h0.x * w; a[1] += h0.y * w; a[2] += h0.z * w; a[3] += h0.w * w;
                a[4] += h1.x * w; a[5] += h1.y * w; a[6] += h1.z * w; a[7] += h1.w * w;
            }
            float* p = p2 + g * 1280 + ks * 320 + jj * 8;
            *(float4*)p       = make_float4(a[0], a[1], a[2], a[3]);
            *(float4*)(p + 4) = make_float4(a[4], a[5], a[6], a[7]);
        }
        __syncthreads();
        // reduce + sigmoid; g==1 (r gate) scales ycT in place, g==0 stores u_
        for (int i = tid; i < 640; i += NTHR) {
            int g = i / 320, rem = i % 320, jj = rem >> 3, r = rem & 7;
            const float* p = p2 + g * 1280;
            float a = p[rem] + p[320 + rem] + p[640 + rem] + p[960 + rem] + (g ? rb2 : ub2)[jj];
            float sg = fast_sigmoid(a);
            if (g) ycT[jj * 8 + r] *= sg;
            else   u_[r * 40 + jj] = sg;
        }
        __syncthreads();

        // ---- n layer1 (K-split 3, 600 thr; ycT already r-scaled) ----
        if (tid < 600)
            gru_l1_single_ks(nw1, ycT, pL1, tid % GU, tid / GU);
        __syncthreads();
        for (int i = tid; i < 1600; i += NTHR) {
            int j = i >> 3;
            hTa[i] = fast_tanh(pL1[i] + pL1[1600 + i] + pL1[3200 + i] + csn[j] + nb1[j]);
        }
        __syncthreads();

        // ---- n layer2 (K-split 8, 320 thr) ----
        if (tid < 320) {
            int jj = tid % 40, ks = tid / 40;   // K=25
            float a[8];
#pragma unroll
            for (int r = 0; r < 8; ++r) a[r] = 0.f;
#pragma unroll 5
            for (int k = ks * 25; k < ks * 25 + 25; ++k) {
                float w = nw2[k * 40 + jj];
                float4 h0 = *(const float4*)(hTa + k * 8);
                float4 h1 = *(const float4*)(hTa + k * 8 + 4);
                a[0] += h0.x * w; a[1] += h0.y * w; a[2] += h0.z * w; a[3] += h0.w * w;
                a[4] += h1.x * w; a[5] += h1.y * w; a[6] += h1.z * w; a[7] += h1.w * w;
            }
            float* p = pn + ks * 320 + jj * 8;
            *(float4*)p       = make_float4(a[0], a[1], a[2], a[3]);
            *(float4*)(p + 4) = make_float4(a[4], a[5], a[6], a[7]);
        }
        __syncthreads();
        // reduce + state update; refresh full ycT y-part (ym+ys) for next step
        if (tid < 320) {
            int jj = tid >> 3, r = tid & 7;
            float a = pn[tid] + pn[320 + tid] + pn[640 + tid] + pn[960 + tid]
                    + pn[1280 + tid] + pn[1600 + tid] + pn[1920 + tid] + pn[2240 + tid] + nb2[jj];
            float val = (jj < LL) ? a : fabsf(a);
            float uu = u_[r * 40 + jj];
            float ynew = (1.f - uu) * val + uu * y[r * 40 + jj];
            y[r * 40 + jj] = ynew;
            ycT[jj * 8 + r] = ynew;
        }
        __syncthreads();
    }

    // ================= z0 head (once) =================
    for (int i = tid; i < ROWS * UNI; i += NTHR) {
        int r = i / UNI, j = i % UNI;
        float a = z0b1[j];
#pragma unroll 4
        for (int k = 0; k < 40; ++k) a += y[r * 40 + k] * z0w1[k * UNI + j];
        hencT[i] = fast_tanh(a);
    }
    __syncthreads();
    for (int i = tid; i < ROWS * 64; i += NTHR) {
        int r = i / 64, j = i % 64;
        float a = z0b2[j];
#pragma unroll 4
        for (int k = 0; k < UNI; ++k) a += hencT[r * UNI + k] * z0w2[k * 64 + j];
        hTa[r * 64 + j] = a;
    }
    __syncthreads();
    if (tid < 256) {
        int r = tid >> 5, j = tid & 31;
        float m = hTa[r * 64 + j];
        float sd = fabsf(hTa[r * 64 + 32 + j]);
        zT[j * 8 + r] = m + eps[(size_t)(b0 + r) * LATD + j] * sd;
    }
    __syncthreads();

    // ---------------- decoder smem layout (aliases P; ddt beyond -> safe) ----------------
    float* dw1   = P;             // 3200
    float* dw2   = P + 3200;      // 10000
    float* dw3   = P + 13200;     // 3200
    float* db1   = P + 16400;     // 100
    float* db2   = P + 16500;     // 100
    float* db3   = P + 16600;     // 32
    float* ow    = P + 16632;     // 4096
    float* ob    = P + 20728;     // 128
    float* h1T   = P + 20856;     // 800
    float* h2T   = P + 21656;     // 800
    float* ztmpT = P + 22456;     // 256
    float* zacc  = P + 22712;     // 256
    float* pd2   = P + 22968;     // 3200 [4][100][8]
    float* pd3   = P + 26168;     // 2560 [10][32][8]

    for (int i = tid; i < 3200;  i += NTHR) { dw1[i] = dw1g[i]; dw3[i] = dw3g[i]; }
    for (int i = tid; i < 10000; i += NTHR) dw2[i] = dw2g[i];
    for (int i = tid; i < 100;   i += NTHR) { db1[i] = db1g[i]; db2[i] = db2g[i]; }
    for (int i = tid; i < 32;    i += NTHR) db3[i] = db3g[i];
    for (int i = tid; i < 4096;  i += NTHR) ow[i] = owg[i];
    for (int i = tid; i < 128;   i += NTHR) ob[i] = obg[i];
    __syncthreads();

    // ================= decoder scan; projection(ti-1) absorbed in stage-1 l3 =================
    for (int ti = 1; ti < TT; ++ti) {
        float dt = ddt[ti - 1];
        dec_eval(dw1, db1, dw2, db2, dw3, zT, h1T, h2T, pd2, pd3, tid,
                 ow, ob, zT, out, b0, ti - 1);
        if (tid < 256) {
            float kv = DEC_K(tid);
            zacc[tid] = kv;
            ztmpT[tid] = zT[tid] + 0.5f * dt * kv;
        }
        __syncthreads();
        dec_eval(dw1, db1, dw2, db2, dw3, ztmpT, h1T, h2T, pd2, pd3, tid,
                 ow, ob, zT, out, b0, -1);
        if (tid < 256) {
            float kv = DEC_K(tid);
            zacc[tid] += 2.f * kv;
            ztmpT[tid] = zT[tid] + 0.5f * dt * kv;
        }
        __syncthreads();
        dec_eval(dw1, db1, dw2, db2, dw3, ztmpT, h1T, h2T, pd2, pd3, tid,
                 ow, ob, zT, out, b0, -1);
        if (tid < 256) {
            float kv = DEC_K(tid);
            zacc[tid] += 2.f * kv;
            ztmpT[tid] = zT[tid] + dt * kv;
        }
        __syncthreads();
        dec_eval(dw1, db1, dw2, db2, dw3, ztmpT, h1T, h2T, pd2, pd3, tid,
                 ow, ob, zT, out, b0, -1);
        if (tid < 256) {
            float kv = DEC_K(tid);
            zT[tid] += dt * (1.f / 6.f) * (zacc[tid] + kv);
        }
        __syncthreads();
    }

    // final projection for ti = TT-1 (zT holds final z)
    if (tid < DD) {
        int d = tid;
        float a[8];
        float b = ob[d];
#pragma unroll
        for (int r = 0; r < 8; ++r) a[r] = b;
#pragma unroll 8
        for (int k = 0; k < LATD; ++k) {
            float w = ow[k * DD + d];
            float4 z0 = *(const float4*)(zT + k * 8);
            float4 z1 = *(const float4*)(zT + k * 8 + 4);
            a[0] += z0.x * w; a[1] += z0.y * w; a[2] += z0.z * w; a[3] += z0.w * w;
            a[4] += z1.x * w; a[5] += z1.y * w; a[6] += z1.z * w; a[7] += z1.w * w;
        }
#pragma unroll
        for (int r = 0; r < 8; ++r)
            out[(size_t)(b0 + r) * (TT * DD) + (size_t)(TT - 1) * DD + d] = a[r];
    }
}

extern "C" void kernel_launch(void* const* d_in, const int* in_sizes, int n_in,
                              void* d_out, int out_size) {
    (void)in_sizes; (void)n_in; (void)out_size;
    size_t smem = (size_t)SM_FLOATS * sizeof(float);
    cudaFuncSetAttribute(latent_ode_main, cudaFuncAttributeMaxDynamicSharedMemorySize, (int)smem);

    colsum_kernel<<<3, GU>>>((const float*)d_in[8], (const float*)d_in[12], (const float*)d_in[16]);

    latent_ode_main<<<NBLK, NTHR, smem>>>(
        (const float*)d_in[0], (const float*)d_in[1], (const int*)d_in[2], (const float*)d_in[3],
        (const float*)d_in[4],  (const float*)d_in[5],  (const float*)d_in[6],  (const float*)d_in[7],
        (const float*)d_in[8],  (const float*)d_in[9],  (const float*)d_in[10], (const float*)d_in[11],
        (const float*)d_in[12], (const float*)d_in[13], (const float*)d_in[14], (const float*)d_in[15],
        (const float*)d_in[16], (const float*)d_in[17], (const float*)d_in[18], (const float*)d_in[19],
        (const float*)d_in[20], (const float*)d_in[21], (const float*)d_in[22], (const float*)d_in[23],
        (const float*)d_in[24], (const float*)d_in[25], (const float*)d_in[26], (const float*)d_in[27],
        (const float*)d_in[28], (const float*)d_in[29], (const float*)d_in[30], (const float*)d_in[31],
        (float*)d_out);
}